// round 13
// baseline (speedup 1.0000x reference)
#include <cuda_runtime.h>
#include <cuda_bf16.h>
#include <cstdint>

#define Bn 2
#define CSn 128
#define CDn 128
#define SDn 8
#define SHn 16
#define SWn 16
#define DDn 16
#define DHn 32
#define DWn 32
#define Pn  (DDn*DHn*DWn)      /* 16384 */
#define Gn 8
#define K3n 27
#define CGn 16                 /* CS/G */
#define NOFF (K3n*3*Gn)        /* 648 */
#define NTAP (Gn*K3n)          /* 216 */
#define WROW 80                /* padded row bytes of A/B smem tiles */
#define WTILE (128*WROW)       /* 10240 B per weight tile */
#define STILE (64*WROW)        /* 5120 B per sample tile */
#define MTILES 6               /* ceil(648/128) m-tiles for offset GEMM */
#define DCN_SMEM (4*WTILE + 4*STILE)   /* 61440 B */

typedef unsigned long long ull;

// ---------------- bf16 helpers ------------------------------------------------
__device__ __forceinline__ uint32_t cvtbf2(float hi, float lo) { // {hi,lo} packed
    uint32_t r;
    asm("cvt.rn.bf16x2.f32 %0, %1, %2;" : "=r"(r) : "f"(hi), "f"(lo));
    return r;
}

// ---------------- cp.async helpers --------------------------------------------
__device__ __forceinline__ void cpasync16(uint32_t saddr, const void* g) {
    asm volatile("cp.async.cg.shared.global [%0], [%1], 16;"
                 :: "r"(saddr), "l"(g));
}
__device__ __forceinline__ void cpcommit() {
    asm volatile("cp.async.commit_group;");
}
__device__ __forceinline__ void cpwait0() {
    asm volatile("cp.async.wait_group 0;" ::: "memory");
}

// ---------------- tensor-core helpers ---------------------------------------
__device__ __forceinline__ void ldsm4(uint32_t* r, uint32_t addr) {
    asm volatile("ldmatrix.sync.aligned.m8n8.x4.shared.b16 {%0,%1,%2,%3},[%4];"
        : "=r"(r[0]), "=r"(r[1]), "=r"(r[2]), "=r"(r[3]) : "r"(addr));
}
__device__ __forceinline__ void mma16816(float* d, const uint32_t* a,
                                         uint32_t b0, uint32_t b1) {
    asm volatile(
        "mma.sync.aligned.m16n8k16.row.col.f32.bf16.bf16.f32 "
        "{%0,%1,%2,%3},{%4,%5,%6,%7},{%8,%9},{%0,%1,%2,%3};"
        : "+f"(d[0]), "+f"(d[1]), "+f"(d[2]), "+f"(d[3])
        : "r"(a[0]), "r"(a[1]), "r"(a[2]), "r"(a[3]), "r"(b0), "r"(b1));
}

// -------- device scratch ----------------------------------------------------
__device__ float g_src_cl[Bn*SDn*SHn*SWn*CSn];   // [b][z][y][x][c]
__device__ float g_up_cl[Bn*Pn*CSn];             // [b][p][c]
__device__ float g_off[Bn*NOFF*Pn];              // [b][o][p]
__device__ __align__(16) uint8_t g_wsplit[(size_t)NTAP*WTILE];       // dcn W hi/lo
__device__ __align__(16) uint8_t g_wosplit[(size_t)MTILES*16*WTILE]; // offset W hi/lo
__device__ __align__(16) __nv_bfloat16 g_cath[(size_t)Bn*Pn*256];    // cat hi [b][p][c]
__device__ __align__(16) __nv_bfloat16 g_catl[(size_t)Bn*Pn*256];    // cat lo

// -------- prep: transposes + bf16 weight splits ------------------------------
__global__ void k_prep(const float* __restrict__ src,
                       const float* __restrict__ woff,
                       const float* __restrict__ wdcn) {
    int i = blockIdx.x * blockDim.x + threadIdx.x;
    const int N1 = Bn*SDn*SHn*SWn*CSn;    // 524288
    const int N3 = NTAP*128*CGn;          // 442368
    const int N4 = MTILES*128*256;        // 196608 (768 o x 256 c)
    if (i < N1) {
        int c = i % CSn;
        int s = (i / CSn) % (SDn*SHn*SWn);
        int b = i / (CSn*SDn*SHn*SWn);
        g_src_cl[i] = src[(b*CSn + c)*(SDn*SHn*SWn) + s];
    } else if (i < N1 + N3) {
        int j = i - N1;
        int cg = j % CGn;
        int o  = (j / CGn) % 128;
        int kk = j / (CGn*128);
        int g = kk / K3n, k = kk % K3n;
        float wv = wdcn[((o*CSn) + g*CGn + cg)*K3n + k];
        __nv_bfloat16 hb = __float2bfloat16(wv);
        __nv_bfloat16 lb = __float2bfloat16(wv - __bfloat162float(hb));
        uint8_t* row = g_wsplit + (size_t)kk*WTILE + o*WROW;
        *(__nv_bfloat16*)(row + cg*2)      = hb;
        *(__nv_bfloat16*)(row + 32 + cg*2) = lb;
    } else if (i < N1 + N3 + N4) {
        int j = i - N1 - N3;
        int c = j % 256;
        int o = j / 256;                  // 0..767 (padded)
        float wv = (o < NOFF) ? woff[o*256 + c] : 0.f;
        __nv_bfloat16 hb = __float2bfloat16(wv);
        __nv_bfloat16 lb = __float2bfloat16(wv - __bfloat162float(hb));
        int mt = o >> 7, kc = c >> 4;
        uint8_t* row = g_wosplit + (size_t)(mt*16 + kc)*WTILE + (o & 127)*WROW;
        *(__nv_bfloat16*)(row + (c & 15)*2)      = hb;
        *(__nv_bfloat16*)(row + 32 + (c & 15)*2) = lb;
    }
}

// -------- trilinear 2x upsample ----------------------------------------------
__global__ void k_upsample() {
    int bp = blockIdx.x;                 // Bn*Pn blocks
    int b = bp / Pn;
    int p = bp % Pn;
    int d = p >> 10, h = (p >> 5) & 31, w = p & 31;

    float zc = d*0.5f - 0.25f, yc = h*0.5f - 0.25f, xc = w*0.5f - 0.25f;
    int zf = (int)floorf(zc), yf = (int)floorf(yc), xf = (int)floorf(xc);
    float fz = zc - zf, fy = yc - yf, fx = xc - xf;
    int z0 = min(max(zf,     0), SDn-1), z1 = min(max(zf + 1, 0), SDn-1);
    int y0 = min(max(yf,     0), SHn-1), y1 = min(max(yf + 1, 0), SHn-1);
    int x0 = min(max(xf,     0), SWn-1), x1 = min(max(xf + 1, 0), SWn-1);

    const float* base = g_src_cl + (size_t)b * (SDn*SHn*SWn) * CSn;
    int c = threadIdx.x;  // 128

    float v000 = base[(z0*256 + y0*16 + x0)*CSn + c];
    float v001 = base[(z0*256 + y0*16 + x1)*CSn + c];
    float v010 = base[(z0*256 + y1*16 + x0)*CSn + c];
    float v011 = base[(z0*256 + y1*16 + x1)*CSn + c];
    float v100 = base[(z1*256 + y0*16 + x0)*CSn + c];
    float v101 = base[(z1*256 + y0*16 + x1)*CSn + c];
    float v110 = base[(z1*256 + y1*16 + x0)*CSn + c];
    float v111 = base[(z1*256 + y1*16 + x1)*CSn + c];

    float r0 = (1.f-fy)*((1.f-fx)*v000 + fx*v001) + fy*((1.f-fx)*v010 + fx*v011);
    float r1 = (1.f-fy)*((1.f-fx)*v100 + fx*v101) + fy*((1.f-fx)*v110 + fx*v111);
    g_up_cl[((size_t)b*Pn + p)*CSn + c] = (1.f-fz)*r0 + fz*r1;
}

// -------- build pre-split bf16 cat image [b][p][256c] ------------------------
__global__ void __launch_bounds__(256) k_cat(const float* __restrict__ dst) {
    __shared__ float cat_s[256*33];
    int blk = blockIdx.x;               // Bn*(Pn/32)
    int b  = blk / (Pn/32);
    int p0 = (blk % (Pn/32)) * 32;
    int t = threadIdx.x;

    for (int i = t; i < 128*32; i += 256) {
        int c = i >> 5, v = i & 31;
        cat_s[c*33 + v] = dst[((size_t)b*CDn + c)*Pn + p0 + v];
    }
    for (int i = t; i < 32*128; i += 256) {
        int v = i >> 7, c = i & 127;
        cat_s[(128 + c)*33 + v] = 2.0f * g_up_cl[((size_t)b*Pn + p0 + v)*CSn + c];
    }
    __syncthreads();

    int v = t & 31, cg = t >> 5;        // 8 groups of 32 channels
    uint32_t oh[16], ol[16];
    #pragma unroll
    for (int j = 0; j < 16; ++j) {
        float f0 = cat_s[(cg*32 + 2*j    )*33 + v];
        float f1 = cat_s[(cg*32 + 2*j + 1)*33 + v];
        uint32_t h = cvtbf2(f1, f0);
        float h0f = __uint_as_float(h << 16);
        float h1f = __uint_as_float(h & 0xffff0000u);
        oh[j] = h;
        ol[j] = cvtbf2(f1 - h1f, f0 - h0f);
    }
    size_t base = ((size_t)b*Pn + p0 + v)*256 + cg*32;
    uint4* dh = (uint4*)&g_cath[base];
    uint4* dl = (uint4*)&g_catl[base];
    #pragma unroll
    for (int j = 0; j < 4; ++j) {
        dh[j] = make_uint4(oh[4*j], oh[4*j+1], oh[4*j+2], oh[4*j+3]);
        dl[j] = make_uint4(ol[4*j], ol[4*j+1], ol[4*j+2], ol[4*j+3]);
    }
}

// -------- offset GEMM on tensor cores, dual N-tile (unchanged from R12) ------
__global__ void __launch_bounds__(256) k_offmma() {
    __shared__ __align__(16) uint8_t sW[2][WTILE];      // 20KB
    __shared__ __align__(16) uint8_t sS[2][2][STILE];   // 20KB

    int blk = blockIdx.x;               // Bn*MTILES*128 = 1536
    int b  = blk / (MTILES*128);
    int r  = blk % (MTILES*128);
    int mt = r / 128;
    int p0 = (r % 128) * 128;
    int t  = threadIdx.x;
    int w  = t >> 5, l = t & 31;

    float dacc[2][8][4];
    #pragma unroll
    for (int tl = 0; tl < 2; ++tl)
        #pragma unroll
        for (int n = 0; n < 8; ++n)
            #pragma unroll
            for (int j = 0; j < 4; ++j) dacc[tl][n][j] = 0.f;

    int btile = t >> 7, brow = (t & 127) >> 1, bpart = t & 1;
    const __nv_bfloat16* catsrc = (bpart ? g_catl : g_cath)
                                + ((size_t)b*Pn + p0 + btile*64 + brow)*256;

    auto domma = [&](int buf) {
        uint32_t sWb = (uint32_t)__cvta_generic_to_shared(&sW[buf][0]);
        uint32_t aaddr = sWb + (w*16 + (l & 15))*WROW + (l >> 4)*16;
        uint32_t ah[4], al[4];
        ldsm4(ah, aaddr);
        ldsm4(al, aaddr + 32);
        uint32_t br = 8*(l >> 4) + (l & 7);
        uint32_t bc = ((l >> 3) & 1)*16;
        #pragma unroll
        for (int tl = 0; tl < 2; ++tl) {
            uint32_t sSb = (uint32_t)__cvta_generic_to_shared(&sS[buf][tl][0]);
            #pragma unroll
            for (int nc = 0; nc < 4; ++nc) {
                uint32_t baddr = sSb + (nc*16 + br)*WROW + bc;
                uint32_t bh[4], bl[4];
                ldsm4(bh, baddr);
                ldsm4(bl, baddr + 32);
                mma16816(dacc[tl][2*nc  ], ah, bh[0], bh[1]);
                mma16816(dacc[tl][2*nc  ], ah, bl[0], bl[1]);
                mma16816(dacc[tl][2*nc  ], al, bh[0], bh[1]);
                mma16816(dacc[tl][2*nc+1], ah, bh[2], bh[3]);
                mma16816(dacc[tl][2*nc+1], ah, bl[2], bl[3]);
                mma16816(dacc[tl][2*nc+1], al, bh[2], bh[3]);
            }
        }
    };

    // prologue: chunk 0
    {
        const uint4* srcW = (const uint4*)(g_wosplit + (size_t)(mt*16)*WTILE);
        uint4* dW = (uint4*)sW[0];
        dW[t] = srcW[t];
        dW[t + 256] = srcW[t + 256];
        if (t < 128) dW[t + 512] = srcW[t + 512];
        const uint4* s = (const uint4*)catsrc;
        uint4* dr = (uint4*)(sS[0][btile] + brow*WROW + bpart*32);
        dr[0] = s[0]; dr[1] = s[1];
    }
    __syncthreads();

    for (int kc = 0; kc < 16; ++kc) {
        int cur = kc & 1;
        bool more = (kc + 1 < 16);
        uint4 wa, wb, wc2, b0, b1;
        if (more) {
            const uint4* srcW = (const uint4*)(g_wosplit + (size_t)(mt*16 + kc + 1)*WTILE);
            wa = srcW[t];
            wb = srcW[t + 256];
            if (t < 128) wc2 = srcW[t + 512];
            const uint4* s = (const uint4*)(catsrc + (kc + 1)*16);
            b0 = s[0]; b1 = s[1];
        }
        domma(cur);
        if (more) {
            int nb = cur ^ 1;
            uint4* dW = (uint4*)sW[nb];
            dW[t] = wa;
            dW[t + 256] = wb;
            if (t < 128) dW[t + 512] = wc2;
            uint4* dr = (uint4*)(sS[nb][btile] + brow*WROW + bpart*32);
            dr[0] = b0; dr[1] = b1;
        }
        __syncthreads();
    }

    // epilogue: write g_off (fp32, guarded o<648), both sub-tiles
    int g = l >> 2, tq = l & 3;
    int o0 = mt*128 + w*16 + g;
    int o1 = o0 + 8;
    #pragma unroll
    for (int tl = 0; tl < 2; ++tl) {
        size_t base0 = ((size_t)b*NOFF + o0)*Pn + p0 + tl*64 + 2*tq;
        size_t base1 = ((size_t)b*NOFF + o1)*Pn + p0 + tl*64 + 2*tq;
        #pragma unroll
        for (int n = 0; n < 8; ++n) {
            if (o0 < NOFF)
                *(float2*)&g_off[base0 + n*8] = make_float2(dacc[tl][n][0], dacc[tl][n][1]);
            if (o1 < NOFF)
                *(float2*)&g_off[base1 + n*8] = make_float2(dacc[tl][n][2], dacc[tl][n][3]);
        }
    }
}

// -------- fused deformable sampling + bf16-split tensor GEMM + ReLU ---------
// block: 64 voxels, 256 threads, 2 CTAs/SM; 4-buffer ring, 2 taps per barrier.
// R13: offsets prefetched a full phase ahead; corner LDGs issued BEFORE the
// dommas (gissue/gconsume split); W staging via cp.async.
__global__ void __launch_bounds__(256, 2) k_dcn(float* __restrict__ out) {
    extern __shared__ __align__(16) uint8_t dyn[];
    uint8_t* sW = dyn;                  // 4 x WTILE
    uint8_t* sS = dyn + 4*WTILE;        // 4 x STILE
    const uint32_t sWu = (uint32_t)__cvta_generic_to_shared(sW);

    int blk = blockIdx.x;               // Bn*(Pn/64) = 512
    int b  = blk >> 8;
    int p0 = (blk & 255) * 64;
    int t  = threadIdx.x;
    int w  = t >> 5, l = t & 31;
    int vv = t >> 2, q = t & 3;

    float dacc[8][4];
    #pragma unroll
    for (int n = 0; n < 8; ++n)
        #pragma unroll
        for (int j = 0; j < 4; ++j) dacc[n][j] = 0.f;

    const size_t offB = (size_t)b * NOFF * Pn;
    const float* upB  = g_up_cl + (size_t)b*Pn*CSn;
    const float* upg4 = upB + q*4;

    int p = p0 + vv;
    int dg = p >> 10, hg = (p >> 5) & 31, wg = p & 31;

    auto loadoffs = [&](int kk, float& z, float& y, float& x) {
        int g = kk / K3n, k = kk % K3n;
        int kz = k/9 - 1, ky = (k/3)%3 - 1, kx = k%3 - 1;
        size_t ob = offB + (size_t)(g*K3n + k)*3*Pn + p;
        z = dg + kz + g_off[ob];
        y = hg + ky + g_off[ob + Pn];
        x = wg + kx + g_off[ob + 2*Pn];
    };

    // W staging via cp.async: 640 uint4 per tile over 256 threads
    auto wasync = [&](int kk, int buf) {
        const char* src = (const char*)(g_wsplit + (size_t)kk*WTILE);
        uint32_t dst = sWu + buf*WTILE;
        cpasync16(dst + t*16,         src + t*16);
        cpasync16(dst + (t+256)*16,   src + (t+256)*16);
        if (t < 128) cpasync16(dst + (t+512)*16, src + (t+512)*16);
    };

    struct GS { float wt[8]; float4 v[8]; };

    // issue: weights + 8 corner LDG.128 into registers (NO consumption)
    auto gissue = [&](int kk, float z, float y, float x, GS& s) {
        int g = kk / K3n;
        const float* upg = upg4 + g*CGn;

        float z0f = floorf(z), y0f = floorf(y), x0f = floorf(x);
        float fz = z - z0f, fy = y - y0f, fx = x - x0f;
        int z0 = (int)z0f, y0 = (int)y0f, x0 = (int)x0f;

        float wz0 = (z0   >= 0 && z0   < DDn) ? 1.f - fz : 0.f;
        float wz1 = (z0+1 >= 0 && z0+1 < DDn) ? fz       : 0.f;
        float wy0 = (y0   >= 0 && y0   < DHn) ? 1.f - fy : 0.f;
        float wy1 = (y0+1 >= 0 && y0+1 < DHn) ? fy       : 0.f;
        float wx0 = (x0   >= 0 && x0   < DWn) ? 1.f - fx : 0.f;
        float wx1 = (x0+1 >= 0 && x0+1 < DWn) ? fx       : 0.f;
        int zi0 = min(max(z0,   0), DDn-1) << 10;
        int zi1 = min(max(z0+1, 0), DDn-1) << 10;
        int yi0 = min(max(y0,   0), DHn-1) << 5;
        int yi1 = min(max(y0+1, 0), DHn-1) << 5;
        int xi0 = min(max(x0,   0), DWn-1);
        int xi1 = min(max(x0+1, 0), DWn-1);
        float w00 = wz0*wy0, w01 = wz0*wy1, w10 = wz1*wy0, w11 = wz1*wy1;
        int   i00 = zi0+yi0, i01 = zi0+yi1, i10 = zi1+yi0, i11 = zi1+yi1;

        #pragma unroll
        for (int cnr = 0; cnr < 8; ++cnr) {
            float wzy = (cnr>>2) ? ((cnr>>1)&1 ? w11 : w10) : ((cnr>>1)&1 ? w01 : w00);
            int   izy = (cnr>>2) ? ((cnr>>1)&1 ? i11 : i10) : ((cnr>>1)&1 ? i01 : i00);
            s.wt[cnr] = wzy * ((cnr&1) ? wx1 : wx0);
            int ci = izy + ((cnr&1) ? xi1 : xi0);
            s.v[cnr] = *(const float4*)(upg + (size_t)ci*CSn);
        }
    };

    // consume: weighted sum, bf16 split, STS
    auto gconsume = [&](GS& s, int buf) {
        float4 sa = make_float4(0.f, 0.f, 0.f, 0.f);
        #pragma unroll
        for (int cnr = 0; cnr < 8; ++cnr) {
            sa.x += s.wt[cnr]*s.v[cnr].x; sa.y += s.wt[cnr]*s.v[cnr].y;
            sa.z += s.wt[cnr]*s.v[cnr].z; sa.w += s.wt[cnr]*s.v[cnr].w;
        }
        uint32_t h01 = cvtbf2(sa.y, sa.x);
        uint32_t h23 = cvtbf2(sa.w, sa.z);
        uint32_t l01 = cvtbf2(sa.y - __uint_as_float(h01 & 0xffff0000u),
                              sa.x - __uint_as_float(h01 << 16));
        uint32_t l23 = cvtbf2(sa.w - __uint_as_float(h23 & 0xffff0000u),
                              sa.z - __uint_as_float(h23 << 16));
        uint8_t* rowp = sS + buf*STILE + vv*WROW + q*8;
        *(uint2*)rowp        = make_uint2(h01, h23);
        *(uint2*)(rowp + 32) = make_uint2(l01, l23);
    };

    auto domma = [&](int buf) {
        uint32_t sWb = sWu + buf*WTILE;
        uint32_t sSb = (uint32_t)__cvta_generic_to_shared(sS + buf*STILE);
        uint32_t aaddr = sWb + (w*16 + (l & 15))*WROW + (l >> 4)*16;
        uint32_t ah[4], al[4];
        ldsm4(ah, aaddr);
        ldsm4(al, aaddr + 32);
        uint32_t brow = 8*(l >> 4) + (l & 7);
        uint32_t bcol = ((l >> 3) & 1)*16;
        #pragma unroll
        for (int nc = 0; nc < 4; ++nc) {
            uint32_t baddr = sSb + (nc*16 + brow)*WROW + bcol;
            uint32_t bh[4], bl[4];
            ldsm4(bh, baddr);
            ldsm4(bl, baddr + 32);
            mma16816(dacc[2*nc  ], ah, bh[0], bh[1]);
            mma16816(dacc[2*nc  ], ah, bl[0], bl[1]);
            mma16816(dacc[2*nc  ], al, bh[0], bh[1]);
            mma16816(dacc[2*nc+1], ah, bh[2], bh[3]);
            mma16816(dacc[2*nc+1], ah, bl[2], bl[3]);
            mma16816(dacc[2*nc+1], al, bh[2], bh[3]);
        }
    };

    float zc, yc, xc, zd, yd, xd;   // offsets for the NEXT phase's 2 gathers

    // ---- prologue: taps 0 and 1 ----
    {
        float za, ya, xa, zb, yb, xb;
        loadoffs(0, za, ya, xa);
        loadoffs(1, zb, yb, xb);
        wasync(0, 0);
        wasync(1, 1);
        cpcommit();
        GS gs;
        gissue(0, za, ya, xa, gs); gconsume(gs, 0);
        gissue(1, zb, yb, xb, gs); gconsume(gs, 1);
        loadoffs(2, zc, yc, xc);
        loadoffs(3, zd, yd, xd);
        cpwait0();
    }
    __syncthreads();

    // ---- main loop: 2 taps per barrier; loads early, consume late ----
    for (int kk = 0; kk < NTAP; kk += 2) {
        bool more = (kk + 2 < NTAP);
        GS gs;
        if (more) {
            gissue(kk + 2, zc, yc, xc, gs);    // corner LDGs fly over domma(a)
            wasync(kk + 2, (kk + 2) & 3);
            wasync(kk + 3, (kk + 3) & 3);
            cpcommit();
        }

        domma(kk & 3);

        GS gs2;
        if (more) {
            gconsume(gs, (kk + 2) & 3);
            gissue(kk + 3, zd, yd, xd, gs2);   // corner LDGs fly over domma(b)
        }

        domma((kk + 1) & 3);

        if (more) {
            gconsume(gs2, (kk + 3) & 3);
            if (kk + 4 < NTAP) {
                loadoffs(kk + 4, zc, yc, xc);  // DRAM latency covered by next phase
                loadoffs(kk + 5, zd, yd, xd);
            }
            cpwait0();
        }
        __syncthreads();
    }

    // ---- epilogue: ReLU + STG.64 ----
    int g = l >> 2, tq = l & 3;
    size_t base0 = ((size_t)b*CDn + w*16 + g)*Pn + p0 + 2*tq;
    size_t base1 = base0 + (size_t)8*Pn;
    #pragma unroll
    for (int n = 0; n < 8; ++n) {
        float2 v0 = make_float2(fmaxf(dacc[n][0], 0.f), fmaxf(dacc[n][1], 0.f));
        float2 v1 = make_float2(fmaxf(dacc[n][2], 0.f), fmaxf(dacc[n][3], 0.f));
        *(float2*)&out[base0 + n*8] = v0;
        *(float2*)&out[base1 + n*8] = v1;
    }
}

extern "C" void kernel_launch(void* const* d_in, const int* in_sizes, int n_in,
                              void* d_out, int out_size) {
    const float* src  = (const float*)d_in[0];   // feat_1x_src [2,128,8,16,16]
    const float* dst  = (const float*)d_in[1];   // feat_2x_dst [2,128,16,32,32]
    const float* woff = (const float*)d_in[2];   // w_offset [648,256]
    const float* wdcn = (const float*)d_in[3];   // w_dcn [128,128,3,3,3]
    float* out = (float*)d_out;

    cudaFuncSetAttribute(k_dcn, cudaFuncAttributeMaxDynamicSharedMemorySize,
                         DCN_SMEM);

    const int NPREP = Bn*SDn*SHn*SWn*CSn + NTAP*128*CGn + MTILES*128*256;
    k_prep     <<<(NPREP + 255)/256, 256>>>(src, woff, wdcn);
    k_upsample <<<Bn*Pn, 128>>>();
    k_cat      <<<Bn*(Pn/32), 256>>>(dst);
    k_offmma   <<<Bn*MTILES*128, 256>>>();
    k_dcn      <<<Bn*(Pn/64), 256, DCN_SMEM>>>(out);
}

// round 14
// speedup vs baseline: 1.1753x; 1.1753x over previous
#include <cuda_runtime.h>
#include <cuda_bf16.h>
#include <cstdint>

#define Bn 2
#define CSn 128
#define CDn 128
#define SDn 8
#define SHn 16
#define SWn 16
#define DDn 16
#define DHn 32
#define DWn 32
#define Pn  (DDn*DHn*DWn)      /* 16384 */
#define Gn 8
#define K3n 27
#define CGn 16                 /* CS/G */
#define NOFF (K3n*3*Gn)        /* 648 */
#define NTAP (Gn*K3n)          /* 216 */
#define WROW 80                /* padded row bytes of A/B smem tiles */
#define WTILE (128*WROW)       /* 10240 B per weight tile */
#define STILE (64*WROW)        /* 5120 B per sample tile */
#define MTILES 6               /* ceil(648/128) m-tiles for offset GEMM */
#define DCN_SMEM (4*WTILE + 4*STILE)   /* 61440 B */

typedef unsigned long long ull;

// ---------------- bf16 helpers ------------------------------------------------
__device__ __forceinline__ uint32_t cvtbf2(float hi, float lo) { // {hi,lo} packed
    uint32_t r;
    asm("cvt.rn.bf16x2.f32 %0, %1, %2;" : "=r"(r) : "f"(hi), "f"(lo));
    return r;
}

// ---------------- cp.async helpers --------------------------------------------
__device__ __forceinline__ void cpasync16(uint32_t saddr, const void* g) {
    asm volatile("cp.async.cg.shared.global [%0], [%1], 16;"
                 :: "r"(saddr), "l"(g));
}
__device__ __forceinline__ void cpcommit() {
    asm volatile("cp.async.commit_group;");
}
__device__ __forceinline__ void cpwait0() {
    asm volatile("cp.async.wait_group 0;" ::: "memory");
}

// ---------------- tensor-core helpers ---------------------------------------
__device__ __forceinline__ void ldsm4(uint32_t* r, uint32_t addr) {
    asm volatile("ldmatrix.sync.aligned.m8n8.x4.shared.b16 {%0,%1,%2,%3},[%4];"
        : "=r"(r[0]), "=r"(r[1]), "=r"(r[2]), "=r"(r[3]) : "r"(addr));
}
__device__ __forceinline__ void mma16816(float* d, const uint32_t* a,
                                         uint32_t b0, uint32_t b1) {
    asm volatile(
        "mma.sync.aligned.m16n8k16.row.col.f32.bf16.bf16.f32 "
        "{%0,%1,%2,%3},{%4,%5,%6,%7},{%8,%9},{%0,%1,%2,%3};"
        : "+f"(d[0]), "+f"(d[1]), "+f"(d[2]), "+f"(d[3])
        : "r"(a[0]), "r"(a[1]), "r"(a[2]), "r"(a[3]), "r"(b0), "r"(b1));
}

// -------- device scratch ----------------------------------------------------
__device__ float g_src_cl[Bn*SDn*SHn*SWn*CSn];   // [b][z][y][x][c]
__device__ float g_up_cl[Bn*Pn*CSn];             // [b][p][c]
__device__ float g_off[Bn*NOFF*Pn];              // [b][o][p]
__device__ __align__(16) uint8_t g_wsplit[(size_t)NTAP*WTILE];       // dcn W hi/lo
__device__ __align__(16) uint8_t g_wosplit[(size_t)MTILES*16*WTILE]; // offset W hi/lo
__device__ __align__(16) __nv_bfloat16 g_cath[(size_t)Bn*Pn*256];    // cat hi [b][p][c]
__device__ __align__(16) __nv_bfloat16 g_catl[(size_t)Bn*Pn*256];    // cat lo

// -------- prep: transposes + bf16 weight splits ------------------------------
__global__ void k_prep(const float* __restrict__ src,
                       const float* __restrict__ woff,
                       const float* __restrict__ wdcn) {
    int i = blockIdx.x * blockDim.x + threadIdx.x;
    const int N1 = Bn*SDn*SHn*SWn*CSn;    // 524288
    const int N3 = NTAP*128*CGn;          // 442368
    const int N4 = MTILES*128*256;        // 196608 (768 o x 256 c)
    if (i < N1) {
        int c = i % CSn;
        int s = (i / CSn) % (SDn*SHn*SWn);
        int b = i / (CSn*SDn*SHn*SWn);
        g_src_cl[i] = src[(b*CSn + c)*(SDn*SHn*SWn) + s];
    } else if (i < N1 + N3) {
        int j = i - N1;
        int cg = j % CGn;
        int o  = (j / CGn) % 128;
        int kk = j / (CGn*128);
        int g = kk / K3n, k = kk % K3n;
        float wv = wdcn[((o*CSn) + g*CGn + cg)*K3n + k];
        __nv_bfloat16 hb = __float2bfloat16(wv);
        __nv_bfloat16 lb = __float2bfloat16(wv - __bfloat162float(hb));
        uint8_t* row = g_wsplit + (size_t)kk*WTILE + o*WROW;
        *(__nv_bfloat16*)(row + cg*2)      = hb;
        *(__nv_bfloat16*)(row + 32 + cg*2) = lb;
    } else if (i < N1 + N3 + N4) {
        int j = i - N1 - N3;
        int c = j % 256;
        int o = j / 256;                  // 0..767 (padded)
        float wv = (o < NOFF) ? woff[o*256 + c] : 0.f;
        __nv_bfloat16 hb = __float2bfloat16(wv);
        __nv_bfloat16 lb = __float2bfloat16(wv - __bfloat162float(hb));
        int mt = o >> 7, kc = c >> 4;
        uint8_t* row = g_wosplit + (size_t)(mt*16 + kc)*WTILE + (o & 127)*WROW;
        *(__nv_bfloat16*)(row + (c & 15)*2)      = hb;
        *(__nv_bfloat16*)(row + 32 + (c & 15)*2) = lb;
    }
}

// -------- trilinear 2x upsample ----------------------------------------------
__global__ void k_upsample() {
    int bp = blockIdx.x;                 // Bn*Pn blocks
    int b = bp / Pn;
    int p = bp % Pn;
    int d = p >> 10, h = (p >> 5) & 31, w = p & 31;

    float zc = d*0.5f - 0.25f, yc = h*0.5f - 0.25f, xc = w*0.5f - 0.25f;
    int zf = (int)floorf(zc), yf = (int)floorf(yc), xf = (int)floorf(xc);
    float fz = zc - zf, fy = yc - yf, fx = xc - xf;
    int z0 = min(max(zf,     0), SDn-1), z1 = min(max(zf + 1, 0), SDn-1);
    int y0 = min(max(yf,     0), SHn-1), y1 = min(max(yf + 1, 0), SHn-1);
    int x0 = min(max(xf,     0), SWn-1), x1 = min(max(xf + 1, 0), SWn-1);

    const float* base = g_src_cl + (size_t)b * (SDn*SHn*SWn) * CSn;
    int c = threadIdx.x;  // 128

    float v000 = base[(z0*256 + y0*16 + x0)*CSn + c];
    float v001 = base[(z0*256 + y0*16 + x1)*CSn + c];
    float v010 = base[(z0*256 + y1*16 + x0)*CSn + c];
    float v011 = base[(z0*256 + y1*16 + x1)*CSn + c];
    float v100 = base[(z1*256 + y0*16 + x0)*CSn + c];
    float v101 = base[(z1*256 + y0*16 + x1)*CSn + c];
    float v110 = base[(z1*256 + y1*16 + x0)*CSn + c];
    float v111 = base[(z1*256 + y1*16 + x1)*CSn + c];

    float r0 = (1.f-fy)*((1.f-fx)*v000 + fx*v001) + fy*((1.f-fx)*v010 + fx*v011);
    float r1 = (1.f-fy)*((1.f-fx)*v100 + fx*v101) + fy*((1.f-fx)*v110 + fx*v111);
    g_up_cl[((size_t)b*Pn + p)*CSn + c] = (1.f-fz)*r0 + fz*r1;
}

// -------- build pre-split bf16 cat image [b][p][256c] ------------------------
__global__ void __launch_bounds__(256) k_cat(const float* __restrict__ dst) {
    __shared__ float cat_s[256*33];
    int blk = blockIdx.x;               // Bn*(Pn/32)
    int b  = blk / (Pn/32);
    int p0 = (blk % (Pn/32)) * 32;
    int t = threadIdx.x;

    for (int i = t; i < 128*32; i += 256) {
        int c = i >> 5, v = i & 31;
        cat_s[c*33 + v] = dst[((size_t)b*CDn + c)*Pn + p0 + v];
    }
    for (int i = t; i < 32*128; i += 256) {
        int v = i >> 7, c = i & 127;
        cat_s[(128 + c)*33 + v] = 2.0f * g_up_cl[((size_t)b*Pn + p0 + v)*CSn + c];
    }
    __syncthreads();

    int v = t & 31, cg = t >> 5;        // 8 groups of 32 channels
    uint32_t oh[16], ol[16];
    #pragma unroll
    for (int j = 0; j < 16; ++j) {
        float f0 = cat_s[(cg*32 + 2*j    )*33 + v];
        float f1 = cat_s[(cg*32 + 2*j + 1)*33 + v];
        uint32_t h = cvtbf2(f1, f0);
        float h0f = __uint_as_float(h << 16);
        float h1f = __uint_as_float(h & 0xffff0000u);
        oh[j] = h;
        ol[j] = cvtbf2(f1 - h1f, f0 - h0f);
    }
    size_t base = ((size_t)b*Pn + p0 + v)*256 + cg*32;
    uint4* dh = (uint4*)&g_cath[base];
    uint4* dl = (uint4*)&g_catl[base];
    #pragma unroll
    for (int j = 0; j < 4; ++j) {
        dh[j] = make_uint4(oh[4*j], oh[4*j+1], oh[4*j+2], oh[4*j+3]);
        dl[j] = make_uint4(ol[4*j], ol[4*j+1], ol[4*j+2], ol[4*j+3]);
    }
}

// -------- offset GEMM on tensor cores, dual N-tile (unchanged from R12) ------
__global__ void __launch_bounds__(256) k_offmma() {
    __shared__ __align__(16) uint8_t sW[2][WTILE];      // 20KB
    __shared__ __align__(16) uint8_t sS[2][2][STILE];   // 20KB

    int blk = blockIdx.x;               // Bn*MTILES*128 = 1536
    int b  = blk / (MTILES*128);
    int r  = blk % (MTILES*128);
    int mt = r / 128;
    int p0 = (r % 128) * 128;
    int t  = threadIdx.x;
    int w  = t >> 5, l = t & 31;

    float dacc[2][8][4];
    #pragma unroll
    for (int tl = 0; tl < 2; ++tl)
        #pragma unroll
        for (int n = 0; n < 8; ++n)
            #pragma unroll
            for (int j = 0; j < 4; ++j) dacc[tl][n][j] = 0.f;

    int btile = t >> 7, brow = (t & 127) >> 1, bpart = t & 1;
    const __nv_bfloat16* catsrc = (bpart ? g_catl : g_cath)
                                + ((size_t)b*Pn + p0 + btile*64 + brow)*256;

    auto domma = [&](int buf) {
        uint32_t sWb = (uint32_t)__cvta_generic_to_shared(&sW[buf][0]);
        uint32_t aaddr = sWb + (w*16 + (l & 15))*WROW + (l >> 4)*16;
        uint32_t ah[4], al[4];
        ldsm4(ah, aaddr);
        ldsm4(al, aaddr + 32);
        uint32_t br = 8*(l >> 4) + (l & 7);
        uint32_t bc = ((l >> 3) & 1)*16;
        #pragma unroll
        for (int tl = 0; tl < 2; ++tl) {
            uint32_t sSb = (uint32_t)__cvta_generic_to_shared(&sS[buf][tl][0]);
            #pragma unroll
            for (int nc = 0; nc < 4; ++nc) {
                uint32_t baddr = sSb + (nc*16 + br)*WROW + bc;
                uint32_t bh[4], bl[4];
                ldsm4(bh, baddr);
                ldsm4(bl, baddr + 32);
                mma16816(dacc[tl][2*nc  ], ah, bh[0], bh[1]);
                mma16816(dacc[tl][2*nc  ], ah, bl[0], bl[1]);
                mma16816(dacc[tl][2*nc  ], al, bh[0], bh[1]);
                mma16816(dacc[tl][2*nc+1], ah, bh[2], bh[3]);
                mma16816(dacc[tl][2*nc+1], ah, bl[2], bl[3]);
                mma16816(dacc[tl][2*nc+1], al, bh[2], bh[3]);
            }
        }
    };

    // prologue: chunk 0
    {
        const uint4* srcW = (const uint4*)(g_wosplit + (size_t)(mt*16)*WTILE);
        uint4* dW = (uint4*)sW[0];
        dW[t] = srcW[t];
        dW[t + 256] = srcW[t + 256];
        if (t < 128) dW[t + 512] = srcW[t + 512];
        const uint4* s = (const uint4*)catsrc;
        uint4* dr = (uint4*)(sS[0][btile] + brow*WROW + bpart*32);
        dr[0] = s[0]; dr[1] = s[1];
    }
    __syncthreads();

    for (int kc = 0; kc < 16; ++kc) {
        int cur = kc & 1;
        bool more = (kc + 1 < 16);
        uint4 wa, wb, wc2, b0, b1;
        if (more) {
            const uint4* srcW = (const uint4*)(g_wosplit + (size_t)(mt*16 + kc + 1)*WTILE);
            wa = srcW[t];
            wb = srcW[t + 256];
            if (t < 128) wc2 = srcW[t + 512];
            const uint4* s = (const uint4*)(catsrc + (kc + 1)*16);
            b0 = s[0]; b1 = s[1];
        }
        domma(cur);
        if (more) {
            int nb = cur ^ 1;
            uint4* dW = (uint4*)sW[nb];
            dW[t] = wa;
            dW[t + 256] = wb;
            if (t < 128) dW[t + 512] = wc2;
            uint4* dr = (uint4*)(sS[nb][btile] + brow*WROW + bpart*32);
            dr[0] = b0; dr[1] = b1;
        }
        __syncthreads();
    }

    // epilogue: write g_off (fp32, guarded o<648), both sub-tiles
    int g = l >> 2, tq = l & 3;
    int o0 = mt*128 + w*16 + g;
    int o1 = o0 + 8;
    #pragma unroll
    for (int tl = 0; tl < 2; ++tl) {
        size_t base0 = ((size_t)b*NOFF + o0)*Pn + p0 + tl*64 + 2*tq;
        size_t base1 = ((size_t)b*NOFF + o1)*Pn + p0 + tl*64 + 2*tq;
        #pragma unroll
        for (int n = 0; n < 8; ++n) {
            if (o0 < NOFF)
                *(float2*)&g_off[base0 + n*8] = make_float2(dacc[tl][n][0], dacc[tl][n][1]);
            if (o1 < NOFF)
                *(float2*)&g_off[base1 + n*8] = make_float2(dacc[tl][n][2], dacc[tl][n][3]);
        }
    }
}

// -------- fused deformable sampling + bf16-split tensor GEMM + ReLU ---------
// block: 64 voxels, 256 threads, 2 CTAs/SM; 4-buffer ring, 2 taps per barrier.
// R14 = R12 gather (fused, transient regs) + offset prefetch 1 phase ahead
//       + cp.async W staging (register-cheap R13 ingredients only).
__global__ void __launch_bounds__(256, 2) k_dcn(float* __restrict__ out) {
    extern __shared__ __align__(16) uint8_t dyn[];
    uint8_t* sW = dyn;                  // 4 x WTILE
    uint8_t* sS = dyn + 4*WTILE;        // 4 x STILE
    const uint32_t sWu = (uint32_t)__cvta_generic_to_shared(sW);

    int blk = blockIdx.x;               // Bn*(Pn/64) = 512
    int b  = blk >> 8;
    int p0 = (blk & 255) * 64;
    int t  = threadIdx.x;
    int w  = t >> 5, l = t & 31;
    int vv = t >> 2, q = t & 3;

    float dacc[8][4];
    #pragma unroll
    for (int n = 0; n < 8; ++n)
        #pragma unroll
        for (int j = 0; j < 4; ++j) dacc[n][j] = 0.f;

    const size_t offB = (size_t)b * NOFF * Pn;
    const float* upB  = g_up_cl + (size_t)b*Pn*CSn;
    const float* upg4 = upB + q*4;

    int p = p0 + vv;
    int dg = p >> 10, hg = (p >> 5) & 31, wg = p & 31;

    auto loadoffs = [&](int kk, float& z, float& y, float& x) {
        int g = kk / K3n, k = kk % K3n;
        int kz = k/9 - 1, ky = (k/3)%3 - 1, kx = k%3 - 1;
        size_t ob = offB + (size_t)(g*K3n + k)*3*Pn + p;
        z = dg + kz + g_off[ob];
        y = hg + ky + g_off[ob + Pn];
        x = wg + kx + g_off[ob + 2*Pn];
    };

    // W staging via cp.async (no register round-trip)
    auto wasync = [&](int kk, int buf) {
        const char* src = (const char*)(g_wsplit + (size_t)kk*WTILE);
        uint32_t dst = sWu + buf*WTILE;
        cpasync16(dst + t*16,         src + t*16);
        cpasync16(dst + (t+256)*16,   src + (t+256)*16);
        if (t < 128) cpasync16(dst + (t+512)*16, src + (t+512)*16);
    };

    // fused gather (R12 form): loads + weighted sum + bf16 split + STS
    auto gather = [&](int kk, float z, float y, float x, int buf) {
        int g = kk / K3n;
        const float* upg = upg4 + g*CGn;

        float z0f = floorf(z), y0f = floorf(y), x0f = floorf(x);
        float fz = z - z0f, fy = y - y0f, fx = x - x0f;
        int z0 = (int)z0f, y0 = (int)y0f, x0 = (int)x0f;

        float wz0 = (z0   >= 0 && z0   < DDn) ? 1.f - fz : 0.f;
        float wz1 = (z0+1 >= 0 && z0+1 < DDn) ? fz       : 0.f;
        float wy0 = (y0   >= 0 && y0   < DHn) ? 1.f - fy : 0.f;
        float wy1 = (y0+1 >= 0 && y0+1 < DHn) ? fy       : 0.f;
        float wx0 = (x0   >= 0 && x0   < DWn) ? 1.f - fx : 0.f;
        float wx1 = (x0+1 >= 0 && x0+1 < DWn) ? fx       : 0.f;
        int zi0 = min(max(z0,   0), DDn-1) << 10;
        int zi1 = min(max(z0+1, 0), DDn-1) << 10;
        int yi0 = min(max(y0,   0), DHn-1) << 5;
        int yi1 = min(max(y0+1, 0), DHn-1) << 5;
        int xi0 = min(max(x0,   0), DWn-1);
        int xi1 = min(max(x0+1, 0), DWn-1);
        float w00 = wz0*wy0, w01 = wz0*wy1, w10 = wz1*wy0, w11 = wz1*wy1;
        int   i00 = zi0+yi0, i01 = zi0+yi1, i10 = zi1+yi0, i11 = zi1+yi1;

        float4 sa = make_float4(0.f, 0.f, 0.f, 0.f);
        #pragma unroll
        for (int cnr = 0; cnr < 8; ++cnr) {
            float wzy = (cnr>>2) ? ((cnr>>1)&1 ? w11 : w10) : ((cnr>>1)&1 ? w01 : w00);
            int   izy = (cnr>>2) ? ((cnr>>1)&1 ? i11 : i10) : ((cnr>>1)&1 ? i01 : i00);
            float wt  = wzy * ((cnr&1) ? wx1 : wx0);
            int   ci  = izy + ((cnr&1) ? xi1 : xi0);
            float4 v = *(const float4*)(upg + (size_t)ci*CSn);
            sa.x += wt*v.x; sa.y += wt*v.y; sa.z += wt*v.z; sa.w += wt*v.w;
        }
        uint32_t h01 = cvtbf2(sa.y, sa.x);
        uint32_t h23 = cvtbf2(sa.w, sa.z);
        uint32_t l01 = cvtbf2(sa.y - __uint_as_float(h01 & 0xffff0000u),
                              sa.x - __uint_as_float(h01 << 16));
        uint32_t l23 = cvtbf2(sa.w - __uint_as_float(h23 & 0xffff0000u),
                              sa.z - __uint_as_float(h23 << 16));
        uint8_t* rowp = sS + buf*STILE + vv*WROW + q*8;
        *(uint2*)rowp        = make_uint2(h01, h23);
        *(uint2*)(rowp + 32) = make_uint2(l01, l23);
    };

    auto domma = [&](int buf) {
        uint32_t sWb = sWu + buf*WTILE;
        uint32_t sSb = (uint32_t)__cvta_generic_to_shared(sS + buf*STILE);
        uint32_t aaddr = sWb + (w*16 + (l & 15))*WROW + (l >> 4)*16;
        uint32_t ah[4], al[4];
        ldsm4(ah, aaddr);
        ldsm4(al, aaddr + 32);
        uint32_t brow = 8*(l >> 4) + (l & 7);
        uint32_t bcol = ((l >> 3) & 1)*16;
        #pragma unroll
        for (int nc = 0; nc < 4; ++nc) {
            uint32_t baddr = sSb + (nc*16 + brow)*WROW + bcol;
            uint32_t bh[4], bl[4];
            ldsm4(bh, baddr);
            ldsm4(bl, baddr + 32);
            mma16816(dacc[2*nc  ], ah, bh[0], bh[1]);
            mma16816(dacc[2*nc  ], ah, bl[0], bl[1]);
            mma16816(dacc[2*nc  ], al, bh[0], bh[1]);
            mma16816(dacc[2*nc+1], ah, bh[2], bh[3]);
            mma16816(dacc[2*nc+1], ah, bl[2], bl[3]);
            mma16816(dacc[2*nc+1], al, bh[2], bh[3]);
        }
    };

    float zc, yc, xc, zd, yd, xd;   // prefetched offsets for next phase

    // ---- prologue: taps 0 and 1 ----
    {
        float za, ya, xa, zb, yb, xb;
        loadoffs(0, za, ya, xa);
        loadoffs(1, zb, yb, xb);
        wasync(0, 0);
        wasync(1, 1);
        cpcommit();
        gather(0, za, ya, xa, 0);
        gather(1, zb, yb, xb, 1);
        loadoffs(2, zc, yc, xc);
        loadoffs(3, zd, yd, xd);
        cpwait0();
    }
    __syncthreads();

    // ---- main loop: 2 taps per barrier ----
    for (int kk = 0; kk < NTAP; kk += 2) {
        bool more = (kk + 2 < NTAP);
        if (more) {
            wasync(kk + 2, (kk + 2) & 3);
            wasync(kk + 3, (kk + 3) & 3);
            cpcommit();
        }

        domma(kk & 3);
        domma((kk + 1) & 3);

        if (more) {
            gather(kk + 2, zc, yc, xc, (kk + 2) & 3);
            gather(kk + 3, zd, yd, xd, (kk + 3) & 3);
            if (kk + 4 < NTAP) {
                loadoffs(kk + 4, zc, yc, xc);  // latency covered by next phase
                loadoffs(kk + 5, zd, yd, xd);
            }
            cpwait0();
        }
        __syncthreads();
    }

    // ---- epilogue: ReLU + STG.64 ----
    int g = l >> 2, tq = l & 3;
    size_t base0 = ((size_t)b*CDn + w*16 + g)*Pn + p0 + 2*tq;
    size_t base1 = base0 + (size_t)8*Pn;
    #pragma unroll
    for (int n = 0; n < 8; ++n) {
        float2 v0 = make_float2(fmaxf(dacc[n][0], 0.f), fmaxf(dacc[n][1], 0.f));
        float2 v1 = make_float2(fmaxf(dacc[n][2], 0.f), fmaxf(dacc[n][3], 0.f));
        *(float2*)&out[base0 + n*8] = v0;
        *(float2*)&out[base1 + n*8] = v1;
    }
}

extern "C" void kernel_launch(void* const* d_in, const int* in_sizes, int n_in,
                              void* d_out, int out_size) {
    const float* src  = (const float*)d_in[0];   // feat_1x_src [2,128,8,16,16]
    const float* dst  = (const float*)d_in[1];   // feat_2x_dst [2,128,16,32,32]
    const float* woff = (const float*)d_in[2];   // w_offset [648,256]
    const float* wdcn = (const float*)d_in[3];   // w_dcn [128,128,3,3,3]
    float* out = (float*)d_out;

    cudaFuncSetAttribute(k_dcn, cudaFuncAttributeMaxDynamicSharedMemorySize,
                         DCN_SMEM);

    const int NPREP = Bn*SDn*SHn*SWn*CSn + NTAP*128*CGn + MTILES*128*256;
    k_prep     <<<(NPREP + 255)/256, 256>>>(src, woff, wdcn);
    k_upsample <<<Bn*Pn, 128>>>();
    k_cat      <<<Bn*(Pn/32), 256>>>(dst);
    k_offmma   <<<Bn*MTILES*128, 256>>>();
    k_dcn      <<<Bn*(Pn/64), 256, DCN_SMEM>>>(out);
}

// round 15
// speedup vs baseline: 1.2653x; 1.0766x over previous
#include <cuda_runtime.h>
#include <cuda_bf16.h>
#include <cstdint>

#define Bn 2
#define CSn 128
#define CDn 128
#define SDn 8
#define SHn 16
#define SWn 16
#define DDn 16
#define DHn 32
#define DWn 32
#define Pn  (DDn*DHn*DWn)      /* 16384 */
#define Gn 8
#define K3n 27
#define CGn 16                 /* CS/G */
#define NOFF (K3n*3*Gn)        /* 648 */
#define NTAP (Gn*K3n)          /* 216 */
#define WROW 80                /* padded row bytes of A/B smem tiles */
#define WTILE (128*WROW)       /* 10240 B per weight tile */
#define STILE (64*WROW)        /* 5120 B per sample tile */
#define MTILES 6               /* ceil(648/128) m-tiles for offset GEMM */
#define DCN_SMEM (4*WTILE + 4*STILE)   /* 61440 B */

typedef unsigned long long ull;

// ---------------- bf16 helpers ------------------------------------------------
__device__ __forceinline__ uint32_t cvtbf2(float hi, float lo) { // {hi,lo} packed
    uint32_t r;
    asm("cvt.rn.bf16x2.f32 %0, %1, %2;" : "=r"(r) : "f"(hi), "f"(lo));
    return r;
}

// ---------------- cp.async helpers --------------------------------------------
__device__ __forceinline__ void cpasync16(uint32_t saddr, const void* g) {
    asm volatile("cp.async.cg.shared.global [%0], [%1], 16;"
                 :: "r"(saddr), "l"(g));
}
__device__ __forceinline__ void cpcommit() {
    asm volatile("cp.async.commit_group;");
}
__device__ __forceinline__ void cpwait0() {
    asm volatile("cp.async.wait_group 0;" ::: "memory");
}

// ---------------- tensor-core helpers ---------------------------------------
__device__ __forceinline__ void ldsm4(uint32_t* r, uint32_t addr) {
    asm volatile("ldmatrix.sync.aligned.m8n8.x4.shared.b16 {%0,%1,%2,%3},[%4];"
        : "=r"(r[0]), "=r"(r[1]), "=r"(r[2]), "=r"(r[3]) : "r"(addr));
}
__device__ __forceinline__ void mma16816(float* d, const uint32_t* a,
                                         uint32_t b0, uint32_t b1) {
    asm volatile(
        "mma.sync.aligned.m16n8k16.row.col.f32.bf16.bf16.f32 "
        "{%0,%1,%2,%3},{%4,%5,%6,%7},{%8,%9},{%0,%1,%2,%3};"
        : "+f"(d[0]), "+f"(d[1]), "+f"(d[2]), "+f"(d[3])
        : "r"(a[0]), "r"(a[1]), "r"(a[2]), "r"(a[3]), "r"(b0), "r"(b1));
}

// -------- device scratch ----------------------------------------------------
__device__ float g_src_cl[Bn*SDn*SHn*SWn*CSn];   // [b][z][y][x][c]
__device__ float g_upg[(size_t)Bn*Gn*Pn*CGn];    // [b][g][p][cg]  (group-major)
__device__ float g_off[Bn*NOFF*Pn];              // [b][o][p]
__device__ __align__(16) uint8_t g_wsplit[(size_t)NTAP*WTILE];       // dcn W hi/lo
__device__ __align__(16) uint8_t g_wosplit[(size_t)MTILES*16*WTILE]; // offset W hi/lo
__device__ __align__(16) __nv_bfloat16 g_cath[(size_t)Bn*Pn*256];    // cat hi [b][p][c]
__device__ __align__(16) __nv_bfloat16 g_catl[(size_t)Bn*Pn*256];    // cat lo

// -------- prep: transposes + bf16 weight splits ------------------------------
__global__ void k_prep(const float* __restrict__ src,
                       const float* __restrict__ woff,
                       const float* __restrict__ wdcn) {
    int i = blockIdx.x * blockDim.x + threadIdx.x;
    const int N1 = Bn*SDn*SHn*SWn*CSn;    // 524288
    const int N3 = NTAP*128*CGn;          // 442368
    const int N4 = MTILES*128*256;        // 196608 (768 o x 256 c)
    if (i < N1) {
        int c = i % CSn;
        int s = (i / CSn) % (SDn*SHn*SWn);
        int b = i / (CSn*SDn*SHn*SWn);
        g_src_cl[i] = src[(b*CSn + c)*(SDn*SHn*SWn) + s];
    } else if (i < N1 + N3) {
        int j = i - N1;
        int cg = j % CGn;
        int o  = (j / CGn) % 128;
        int kk = j / (CGn*128);
        int g = kk / K3n, k = kk % K3n;
        float wv = wdcn[((o*CSn) + g*CGn + cg)*K3n + k];
        __nv_bfloat16 hb = __float2bfloat16(wv);
        __nv_bfloat16 lb = __float2bfloat16(wv - __bfloat162float(hb));
        uint8_t* row = g_wsplit + (size_t)kk*WTILE + o*WROW;
        *(__nv_bfloat16*)(row + cg*2)      = hb;
        *(__nv_bfloat16*)(row + 32 + cg*2) = lb;
    } else if (i < N1 + N3 + N4) {
        int j = i - N1 - N3;
        int c = j % 256;
        int o = j / 256;                  // 0..767 (padded)
        float wv = (o < NOFF) ? woff[o*256 + c] : 0.f;
        __nv_bfloat16 hb = __float2bfloat16(wv);
        __nv_bfloat16 lb = __float2bfloat16(wv - __bfloat162float(hb));
        int mt = o >> 7, kc = c >> 4;
        uint8_t* row = g_wosplit + (size_t)(mt*16 + kc)*WTILE + (o & 127)*WROW;
        *(__nv_bfloat16*)(row + (c & 15)*2)      = hb;
        *(__nv_bfloat16*)(row + 32 + (c & 15)*2) = lb;
    }
}

// -------- trilinear 2x upsample -> group-major layout --------------------------
__global__ void k_upsample() {
    int bp = blockIdx.x;                 // Bn*Pn blocks
    int b = bp / Pn;
    int p = bp % Pn;
    int d = p >> 10, h = (p >> 5) & 31, w = p & 31;

    float zc = d*0.5f - 0.25f, yc = h*0.5f - 0.25f, xc = w*0.5f - 0.25f;
    int zf = (int)floorf(zc), yf = (int)floorf(yc), xf = (int)floorf(xc);
    float fz = zc - zf, fy = yc - yf, fx = xc - xf;
    int z0 = min(max(zf,     0), SDn-1), z1 = min(max(zf + 1, 0), SDn-1);
    int y0 = min(max(yf,     0), SHn-1), y1 = min(max(yf + 1, 0), SHn-1);
    int x0 = min(max(xf,     0), SWn-1), x1 = min(max(xf + 1, 0), SWn-1);

    const float* base = g_src_cl + (size_t)b * (SDn*SHn*SWn) * CSn;
    int c = threadIdx.x;  // 128

    float v000 = base[(z0*256 + y0*16 + x0)*CSn + c];
    float v001 = base[(z0*256 + y0*16 + x1)*CSn + c];
    float v010 = base[(z0*256 + y1*16 + x0)*CSn + c];
    float v011 = base[(z0*256 + y1*16 + x1)*CSn + c];
    float v100 = base[(z1*256 + y0*16 + x0)*CSn + c];
    float v101 = base[(z1*256 + y0*16 + x1)*CSn + c];
    float v110 = base[(z1*256 + y1*16 + x0)*CSn + c];
    float v111 = base[(z1*256 + y1*16 + x1)*CSn + c];

    float r0 = (1.f-fy)*((1.f-fx)*v000 + fx*v001) + fy*((1.f-fx)*v010 + fx*v011);
    float r1 = (1.f-fy)*((1.f-fx)*v100 + fx*v101) + fy*((1.f-fx)*v110 + fx*v111);
    g_upg[((size_t)(b*Gn + (c >> 4))*Pn + p)*CGn + (c & 15)] = (1.f-fz)*r0 + fz*r1;
}

// -------- build pre-split bf16 cat image [b][p][256c] ------------------------
__global__ void __launch_bounds__(256) k_cat(const float* __restrict__ dst) {
    __shared__ float cat_s[256*33];
    int blk = blockIdx.x;               // Bn*(Pn/32)
    int b  = blk / (Pn/32);
    int p0 = (blk % (Pn/32)) * 32;
    int t = threadIdx.x;

    for (int i = t; i < 128*32; i += 256) {
        int c = i >> 5, v = i & 31;
        cat_s[c*33 + v] = dst[((size_t)b*CDn + c)*Pn + p0 + v];
    }
    for (int i = t; i < 32*128; i += 256) {
        int v = i >> 7, c = i & 127;
        cat_s[(128 + c)*33 + v] =
            2.0f * g_upg[((size_t)(b*Gn + (c >> 4))*Pn + p0 + v)*CGn + (c & 15)];
    }
    __syncthreads();

    int v = t & 31, cg = t >> 5;        // 8 groups of 32 channels
    uint32_t oh[16], ol[16];
    #pragma unroll
    for (int j = 0; j < 16; ++j) {
        float f0 = cat_s[(cg*32 + 2*j    )*33 + v];
        float f1 = cat_s[(cg*32 + 2*j + 1)*33 + v];
        uint32_t h = cvtbf2(f1, f0);
        float h0f = __uint_as_float(h << 16);
        float h1f = __uint_as_float(h & 0xffff0000u);
        oh[j] = h;
        ol[j] = cvtbf2(f1 - h1f, f0 - h0f);
    }
    size_t base = ((size_t)b*Pn + p0 + v)*256 + cg*32;
    uint4* dh = (uint4*)&g_cath[base];
    uint4* dl = (uint4*)&g_catl[base];
    #pragma unroll
    for (int j = 0; j < 4; ++j) {
        dh[j] = make_uint4(oh[4*j], oh[4*j+1], oh[4*j+2], oh[4*j+3]);
        dl[j] = make_uint4(ol[4*j], ol[4*j+1], ol[4*j+2], ol[4*j+3]);
    }
}

// -------- offset GEMM on tensor cores, dual N-tile, 4Mx2N warp grid ----------
__global__ void __launch_bounds__(256) k_offmma() {
    __shared__ __align__(16) uint8_t sW[2][WTILE];      // 20KB
    __shared__ __align__(16) uint8_t sS[2][2][STILE];   // 20KB

    int blk = blockIdx.x;               // Bn*MTILES*128 = 1536
    int b  = blk / (MTILES*128);
    int r  = blk % (MTILES*128);
    int mt = r / 128;
    int p0 = (r % 128) * 128;
    int t  = threadIdx.x;
    int w  = t >> 5, l = t & 31;
    int wm = w & 3, wn = w >> 2;        // warp = 32 o x 64 p

    float dacc[2][8][4];
    #pragma unroll
    for (int mi = 0; mi < 2; ++mi)
        #pragma unroll
        for (int n = 0; n < 8; ++n)
            #pragma unroll
            for (int j = 0; j < 4; ++j) dacc[mi][n][j] = 0.f;

    int btile = t >> 7, brow = (t & 127) >> 1, bpart = t & 1;
    const __nv_bfloat16* catsrc = (bpart ? g_catl : g_cath)
                                + ((size_t)b*Pn + p0 + btile*64 + brow)*256;

    auto domma = [&](int buf) {
        uint32_t sWb = (uint32_t)__cvta_generic_to_shared(&sW[buf][0]);
        uint32_t ah[2][4], al[2][4];
        #pragma unroll
        for (int mi = 0; mi < 2; ++mi) {
            uint32_t aaddr = sWb + (wm*32 + mi*16 + (l & 15))*WROW + (l >> 4)*16;
            ldsm4(ah[mi], aaddr);
            ldsm4(al[mi], aaddr + 32);
        }
        uint32_t br = 8*(l >> 4) + (l & 7);
        uint32_t bc = ((l >> 3) & 1)*16;
        uint32_t sSb = (uint32_t)__cvta_generic_to_shared(&sS[buf][wn][0]);
        #pragma unroll
        for (int nc = 0; nc < 4; ++nc) {
            uint32_t baddr = sSb + (nc*16 + br)*WROW + bc;
            uint32_t bh[4], bl[4];
            ldsm4(bh, baddr);
            ldsm4(bl, baddr + 32);
            #pragma unroll
            for (int mi = 0; mi < 2; ++mi) {
                mma16816(dacc[mi][2*nc  ], ah[mi], bh[0], bh[1]);
                mma16816(dacc[mi][2*nc  ], ah[mi], bl[0], bl[1]);
                mma16816(dacc[mi][2*nc  ], al[mi], bh[0], bh[1]);
                mma16816(dacc[mi][2*nc+1], ah[mi], bh[2], bh[3]);
                mma16816(dacc[mi][2*nc+1], ah[mi], bl[2], bl[3]);
                mma16816(dacc[mi][2*nc+1], al[mi], bh[2], bh[3]);
            }
        }
    };

    // prologue: chunk 0
    {
        const uint4* srcW = (const uint4*)(g_wosplit + (size_t)(mt*16)*WTILE);
        uint4* dW = (uint4*)sW[0];
        dW[t] = srcW[t];
        dW[t + 256] = srcW[t + 256];
        if (t < 128) dW[t + 512] = srcW[t + 512];
        const uint4* s = (const uint4*)catsrc;
        uint4* dr = (uint4*)(sS[0][btile] + brow*WROW + bpart*32);
        dr[0] = s[0]; dr[1] = s[1];
    }
    __syncthreads();

    for (int kc = 0; kc < 16; ++kc) {
        int cur = kc & 1;
        bool more = (kc + 1 < 16);
        uint4 wa, wb, wc2, b0, b1;
        if (more) {
            const uint4* srcW = (const uint4*)(g_wosplit + (size_t)(mt*16 + kc + 1)*WTILE);
            wa = srcW[t];
            wb = srcW[t + 256];
            if (t < 128) wc2 = srcW[t + 512];
            const uint4* s = (const uint4*)(catsrc + (kc + 1)*16);
            b0 = s[0]; b1 = s[1];
        }
        domma(cur);
        if (more) {
            int nb = cur ^ 1;
            uint4* dW = (uint4*)sW[nb];
            dW[t] = wa;
            dW[t + 256] = wb;
            if (t < 128) dW[t + 512] = wc2;
            uint4* dr = (uint4*)(sS[nb][btile] + brow*WROW + bpart*32);
            dr[0] = b0; dr[1] = b1;
        }
        __syncthreads();
    }

    // epilogue: write g_off (fp32, guarded o<648)
    int g = l >> 2, tq = l & 3;
    int pcb = p0 + wn*64 + 2*tq;
    #pragma unroll
    for (int mi = 0; mi < 2; ++mi) {
        int o0 = mt*128 + wm*32 + mi*16 + g;
        int o1 = o0 + 8;
        size_t base0 = ((size_t)b*NOFF + o0)*Pn + pcb;
        size_t base1 = ((size_t)b*NOFF + o1)*Pn + pcb;
        #pragma unroll
        for (int n = 0; n < 8; ++n) {
            if (o0 < NOFF)
                *(float2*)&g_off[base0 + n*8] = make_float2(dacc[mi][n][0], dacc[mi][n][1]);
            if (o1 < NOFF)
                *(float2*)&g_off[base1 + n*8] = make_float2(dacc[mi][n][2], dacc[mi][n][3]);
        }
    }
}

// -------- fused deformable sampling + bf16-split tensor GEMM + ReLU ---------
// block: 64 voxels, 256 threads, 2 CTAs/SM; 4-buffer ring, 2 taps per barrier.
// R15: gather reads group-major g_upg (dx corner pairs share 128B lines).
__global__ void __launch_bounds__(256, 2) k_dcn(float* __restrict__ out) {
    extern __shared__ __align__(16) uint8_t dyn[];
    uint8_t* sW = dyn;                  // 4 x WTILE
    uint8_t* sS = dyn + 4*WTILE;        // 4 x STILE
    const uint32_t sWu = (uint32_t)__cvta_generic_to_shared(sW);

    int blk = blockIdx.x;               // Bn*(Pn/64) = 512
    int b  = blk >> 8;
    int p0 = (blk & 255) * 64;
    int t  = threadIdx.x;
    int w  = t >> 5, l = t & 31;
    int vv = t >> 2, q = t & 3;

    float dacc[8][4];
    #pragma unroll
    for (int n = 0; n < 8; ++n)
        #pragma unroll
        for (int j = 0; j < 4; ++j) dacc[n][j] = 0.f;

    const size_t offB = (size_t)b * NOFF * Pn;
    const float* upg4 = g_upg + (size_t)(b*Gn)*Pn*CGn + q*4;

    int p = p0 + vv;
    int dg = p >> 10, hg = (p >> 5) & 31, wg = p & 31;

    auto loadoffs = [&](int kk, float& z, float& y, float& x) {
        int g = kk / K3n, k = kk % K3n;
        int kz = k/9 - 1, ky = (k/3)%3 - 1, kx = k%3 - 1;
        size_t ob = offB + (size_t)(g*K3n + k)*3*Pn + p;
        z = dg + kz + g_off[ob];
        y = hg + ky + g_off[ob + Pn];
        x = wg + kx + g_off[ob + 2*Pn];
    };

    // W staging via cp.async (no register round-trip)
    auto wasync = [&](int kk, int buf) {
        const char* src = (const char*)(g_wsplit + (size_t)kk*WTILE);
        uint32_t dst = sWu + buf*WTILE;
        cpasync16(dst + t*16,         src + t*16);
        cpasync16(dst + (t+256)*16,   src + (t+256)*16);
        if (t < 128) cpasync16(dst + (t+512)*16, src + (t+512)*16);
    };

    // fused gather: loads + weighted sum + bf16 split + STS
    auto gather = [&](int kk, float z, float y, float x, int buf) {
        int g = kk / K3n;
        const float* upg = upg4 + (size_t)g*Pn*CGn;

        float z0f = floorf(z), y0f = floorf(y), x0f = floorf(x);
        float fz = z - z0f, fy = y - y0f, fx = x - x0f;
        int z0 = (int)z0f, y0 = (int)y0f, x0 = (int)x0f;

        float wz0 = (z0   >= 0 && z0   < DDn) ? 1.f - fz : 0.f;
        float wz1 = (z0+1 >= 0 && z0+1 < DDn) ? fz       : 0.f;
        float wy0 = (y0   >= 0 && y0   < DHn) ? 1.f - fy : 0.f;
        float wy1 = (y0+1 >= 0 && y0+1 < DHn) ? fy       : 0.f;
        float wx0 = (x0   >= 0 && x0   < DWn) ? 1.f - fx : 0.f;
        float wx1 = (x0+1 >= 0 && x0+1 < DWn) ? fx       : 0.f;
        int zi0 = min(max(z0,   0), DDn-1) << 10;
        int zi1 = min(max(z0+1, 0), DDn-1) << 10;
        int yi0 = min(max(y0,   0), DHn-1) << 5;
        int yi1 = min(max(y0+1, 0), DHn-1) << 5;
        int xi0 = min(max(x0,   0), DWn-1);
        int xi1 = min(max(x0+1, 0), DWn-1);
        float w00 = wz0*wy0, w01 = wz0*wy1, w10 = wz1*wy0, w11 = wz1*wy1;
        int   i00 = zi0+yi0, i01 = zi0+yi1, i10 = zi1+yi0, i11 = zi1+yi1;

        float4 sa = make_float4(0.f, 0.f, 0.f, 0.f);
        #pragma unroll
        for (int cnr = 0; cnr < 8; ++cnr) {
            float wzy = (cnr>>2) ? ((cnr>>1)&1 ? w11 : w10) : ((cnr>>1)&1 ? w01 : w00);
            int   izy = (cnr>>2) ? ((cnr>>1)&1 ? i11 : i10) : ((cnr>>1)&1 ? i01 : i00);
            float wt  = wzy * ((cnr&1) ? wx1 : wx0);
            int   ci  = izy + ((cnr&1) ? xi1 : xi0);
            float4 v = *(const float4*)(upg + (size_t)ci*CGn);
            sa.x += wt*v.x; sa.y += wt*v.y; sa.z += wt*v.z; sa.w += wt*v.w;
        }
        uint32_t h01 = cvtbf2(sa.y, sa.x);
        uint32_t h23 = cvtbf2(sa.w, sa.z);
        uint32_t l01 = cvtbf2(sa.y - __uint_as_float(h01 & 0xffff0000u),
                              sa.x - __uint_as_float(h01 << 16));
        uint32_t l23 = cvtbf2(sa.w - __uint_as_float(h23 & 0xffff0000u),
                              sa.z - __uint_as_float(h23 << 16));
        uint8_t* rowp = sS + buf*STILE + vv*WROW + q*8;
        *(uint2*)rowp        = make_uint2(h01, h23);
        *(uint2*)(rowp + 32) = make_uint2(l01, l23);
    };

    auto domma = [&](int buf) {
        uint32_t sWb = sWu + buf*WTILE;
        uint32_t sSb = (uint32_t)__cvta_generic_to_shared(sS + buf*STILE);
        uint32_t aaddr = sWb + (w*16 + (l & 15))*WROW + (l >> 4)*16;
        uint32_t ah[4], al[4];
        ldsm4(ah, aaddr);
        ldsm4(al, aaddr + 32);
        uint32_t brow = 8*(l >> 4) + (l & 7);
        uint32_t bcol = ((l >> 3) & 1)*16;
        #pragma unroll
        for (int nc = 0; nc < 4; ++nc) {
            uint32_t baddr = sSb + (nc*16 + brow)*WROW + bcol;
            uint32_t bh[4], bl[4];
            ldsm4(bh, baddr);
            ldsm4(bl, baddr + 32);
            mma16816(dacc[2*nc  ], ah, bh[0], bh[1]);
            mma16816(dacc[2*nc  ], ah, bl[0], bl[1]);
            mma16816(dacc[2*nc  ], al, bh[0], bh[1]);
            mma16816(dacc[2*nc+1], ah, bh[2], bh[3]);
            mma16816(dacc[2*nc+1], ah, bl[2], bl[3]);
            mma16816(dacc[2*nc+1], al, bh[2], bh[3]);
        }
    };

    float zc, yc, xc, zd, yd, xd;   // prefetched offsets for next phase

    // ---- prologue: taps 0 and 1 ----
    {
        float za, ya, xa, zb, yb, xb;
        loadoffs(0, za, ya, xa);
        loadoffs(1, zb, yb, xb);
        wasync(0, 0);
        wasync(1, 1);
        cpcommit();
        gather(0, za, ya, xa, 0);
        gather(1, zb, yb, xb, 1);
        loadoffs(2, zc, yc, xc);
        loadoffs(3, zd, yd, xd);
        cpwait0();
    }
    __syncthreads();

    // ---- main loop: 2 taps per barrier ----
    for (int kk = 0; kk < NTAP; kk += 2) {
        bool more = (kk + 2 < NTAP);
        if (more) {
            wasync(kk + 2, (kk + 2) & 3);
            wasync(kk + 3, (kk + 3) & 3);
            cpcommit();
        }

        domma(kk & 3);
        domma((kk + 1) & 3);

        if (more) {
            gather(kk + 2, zc, yc, xc, (kk + 2) & 3);
            gather(kk + 3, zd, yd, xd, (kk + 3) & 3);
            if (kk + 4 < NTAP) {
                loadoffs(kk + 4, zc, yc, xc);  // latency covered by next phase
                loadoffs(kk + 5, zd, yd, xd);
            }
            cpwait0();
        }
        __syncthreads();
    }

    // ---- epilogue: ReLU + STG.64 ----
    int g = l >> 2, tq = l & 3;
    size_t base0 = ((size_t)b*CDn + w*16 + g)*Pn + p0 + 2*tq;
    size_t base1 = base0 + (size_t)8*Pn;
    #pragma unroll
    for (int n = 0; n < 8; ++n) {
        float2 v0 = make_float2(fmaxf(dacc[n][0], 0.f), fmaxf(dacc[n][1], 0.f));
        float2 v1 = make_float2(fmaxf(dacc[n][2], 0.f), fmaxf(dacc[n][3], 0.f));
        *(float2*)&out[base0 + n*8] = v0;
        *(float2*)&out[base1 + n*8] = v1;
    }
}

extern "C" void kernel_launch(void* const* d_in, const int* in_sizes, int n_in,
                              void* d_out, int out_size) {
    const float* src  = (const float*)d_in[0];   // feat_1x_src [2,128,8,16,16]
    const float* dst  = (const float*)d_in[1];   // feat_2x_dst [2,128,16,32,32]
    const float* woff = (const float*)d_in[2];   // w_offset [648,256]
    const float* wdcn = (const float*)d_in[3];   // w_dcn [128,128,3,3,3]
    float* out = (float*)d_out;

    cudaFuncSetAttribute(k_dcn, cudaFuncAttributeMaxDynamicSharedMemorySize,
                         DCN_SMEM);

    const int NPREP = Bn*SDn*SHn*SWn*CSn + NTAP*128*CGn + MTILES*128*256;
    k_prep     <<<(NPREP + 255)/256, 256>>>(src, woff, wdcn);
    k_upsample <<<Bn*Pn, 128>>>();
    k_cat      <<<Bn*(Pn/32), 256>>>(dst);
    k_offmma   <<<Bn*MTILES*128, 256>>>();
    k_dcn      <<<Bn*(Pn/64), 256, DCN_SMEM>>>(out);
}

// round 16
// speedup vs baseline: 1.3099x; 1.0353x over previous
#include <cuda_runtime.h>
#include <cuda_bf16.h>
#include <cstdint>

#define Bn 2
#define CSn 128
#define CDn 128
#define SDn 8
#define SHn 16
#define SWn 16
#define DDn 16
#define DHn 32
#define DWn 32
#define Pn  (DDn*DHn*DWn)      /* 16384 */
#define Gn 8
#define K3n 27
#define CGn 16                 /* CS/G */
#define NOFF (K3n*3*Gn)        /* 648 */
#define NTAP (Gn*K3n)          /* 216 */
#define WROW 80                /* padded row bytes of A/B smem tiles */
#define WTILE (128*WROW)       /* 10240 B per weight tile */
#define STILE (64*WROW)        /* 5120 B per sample tile */
#define MTILES 6               /* ceil(648/128) m-tiles for offset GEMM */
#define DCN_SMEM (6*WTILE + 6*STILE)   /* 92160 B */

typedef unsigned long long ull;

// ---------------- bf16 helpers ------------------------------------------------
__device__ __forceinline__ uint32_t cvtbf2(float hi, float lo) { // {hi,lo} packed
    uint32_t r;
    asm("cvt.rn.bf16x2.f32 %0, %1, %2;" : "=r"(r) : "f"(hi), "f"(lo));
    return r;
}

// ---------------- cp.async helpers --------------------------------------------
__device__ __forceinline__ void cpasync16(uint32_t saddr, const void* g) {
    asm volatile("cp.async.cg.shared.global [%0], [%1], 16;"
                 :: "r"(saddr), "l"(g));
}
__device__ __forceinline__ void cpcommit() {
    asm volatile("cp.async.commit_group;");
}
__device__ __forceinline__ void cpwait0() {
    asm volatile("cp.async.wait_group 0;" ::: "memory");
}

// ---------------- tensor-core helpers ---------------------------------------
__device__ __forceinline__ void ldsm4(uint32_t* r, uint32_t addr) {
    asm volatile("ldmatrix.sync.aligned.m8n8.x4.shared.b16 {%0,%1,%2,%3},[%4];"
        : "=r"(r[0]), "=r"(r[1]), "=r"(r[2]), "=r"(r[3]) : "r"(addr));
}
__device__ __forceinline__ void mma16816(float* d, const uint32_t* a,
                                         uint32_t b0, uint32_t b1) {
    asm volatile(
        "mma.sync.aligned.m16n8k16.row.col.f32.bf16.bf16.f32 "
        "{%0,%1,%2,%3},{%4,%5,%6,%7},{%8,%9},{%0,%1,%2,%3};"
        : "+f"(d[0]), "+f"(d[1]), "+f"(d[2]), "+f"(d[3])
        : "r"(a[0]), "r"(a[1]), "r"(a[2]), "r"(a[3]), "r"(b0), "r"(b1));
}

// -------- device scratch ----------------------------------------------------
__device__ float g_src_cl[Bn*SDn*SHn*SWn*CSn];   // [b][z][y][x][c]
__device__ float g_upg[(size_t)Bn*Gn*Pn*CGn];    // [b][g][p][cg]  (group-major)
__device__ float g_off[Bn*NOFF*Pn];              // [b][o][p]
__device__ __align__(16) uint8_t g_wsplit[(size_t)NTAP*WTILE];       // dcn W hi/lo
__device__ __align__(16) uint8_t g_wosplit[(size_t)MTILES*16*WTILE]; // offset W hi/lo
__device__ __align__(16) __nv_bfloat16 g_cath[(size_t)Bn*Pn*256];    // cat hi [b][p][c]
__device__ __align__(16) __nv_bfloat16 g_catl[(size_t)Bn*Pn*256];    // cat lo

// -------- prep: transposes + bf16 weight splits ------------------------------
__global__ void k_prep(const float* __restrict__ src,
                       const float* __restrict__ woff,
                       const float* __restrict__ wdcn) {
    int i = blockIdx.x * blockDim.x + threadIdx.x;
    const int N1 = Bn*SDn*SHn*SWn*CSn;    // 524288
    const int N3 = NTAP*128*CGn;          // 442368
    const int N4 = MTILES*128*256;        // 196608 (768 o x 256 c)
    if (i < N1) {
        int c = i % CSn;
        int s = (i / CSn) % (SDn*SHn*SWn);
        int b = i / (CSn*SDn*SHn*SWn);
        g_src_cl[i] = src[(b*CSn + c)*(SDn*SHn*SWn) + s];
    } else if (i < N1 + N3) {
        int j = i - N1;
        int cg = j % CGn;
        int o  = (j / CGn) % 128;
        int kk = j / (CGn*128);
        int g = kk / K3n, k = kk % K3n;
        float wv = wdcn[((o*CSn) + g*CGn + cg)*K3n + k];
        __nv_bfloat16 hb = __float2bfloat16(wv);
        __nv_bfloat16 lb = __float2bfloat16(wv - __bfloat162float(hb));
        uint8_t* row = g_wsplit + (size_t)kk*WTILE + o*WROW;
        *(__nv_bfloat16*)(row + cg*2)      = hb;
        *(__nv_bfloat16*)(row + 32 + cg*2) = lb;
    } else if (i < N1 + N3 + N4) {
        int j = i - N1 - N3;
        int c = j % 256;
        int o = j / 256;                  // 0..767 (padded)
        float wv = (o < NOFF) ? woff[o*256 + c] : 0.f;
        __nv_bfloat16 hb = __float2bfloat16(wv);
        __nv_bfloat16 lb = __float2bfloat16(wv - __bfloat162float(hb));
        int mt = o >> 7, kc = c >> 4;
        uint8_t* row = g_wosplit + (size_t)(mt*16 + kc)*WTILE + (o & 127)*WROW;
        *(__nv_bfloat16*)(row + (c & 15)*2)      = hb;
        *(__nv_bfloat16*)(row + 32 + (c & 15)*2) = lb;
    }
}

// -------- fused upsample + cat: writes g_upg, g_cath, g_catl ------------------
// block: 32 voxels, 256 threads; thread = (v = t&31, g = t>>5) -> 16 channels.
__global__ void __launch_bounds__(256) k_up(const float* __restrict__ dst) {
    __shared__ float cat_s[128*33];     // dst staging [c][v], padded
    int blk = blockIdx.x;               // Bn*(Pn/32) = 1024
    int b  = blk / (Pn/32);
    int p0 = (blk % (Pn/32)) * 32;
    int t  = threadIdx.x;
    int v  = t & 31, g = t >> 5;

    // stage dst channels (coalesced on v)
    for (int i = t; i < 128*32; i += 256) {
        int c = i >> 5, vv = i & 31;
        cat_s[c*33 + vv] = dst[((size_t)b*CDn + c)*Pn + p0 + vv];
    }

    // trilinear upsample: voxel p, 16 channels of group g
    int p = p0 + v;
    int d = p >> 10, h = (p >> 5) & 31, w = p & 31;
    float zc = d*0.5f - 0.25f, yc = h*0.5f - 0.25f, xc = w*0.5f - 0.25f;
    int zf = (int)floorf(zc), yf = (int)floorf(yc), xf = (int)floorf(xc);
    float fz = zc - zf, fy = yc - yf, fx = xc - xf;
    int z0 = min(max(zf,     0), SDn-1), z1 = min(max(zf + 1, 0), SDn-1);
    int y0 = min(max(yf,     0), SHn-1), y1 = min(max(yf + 1, 0), SHn-1);
    int x0 = min(max(xf,     0), SWn-1), x1 = min(max(xf + 1, 0), SWn-1);

    const float* base = g_src_cl + (size_t)b*(SDn*SHn*SWn)*CSn + g*CGn;
    float4 acc[4];
    #pragma unroll
    for (int j = 0; j < 4; ++j) acc[j] = make_float4(0.f, 0.f, 0.f, 0.f);
    #pragma unroll
    for (int cnr = 0; cnr < 8; ++cnr) {
        int dz = cnr>>2, dy = (cnr>>1)&1, dx = cnr&1;
        float wt = (dz ? fz : 1.f-fz) * (dy ? fy : 1.f-fy) * (dx ? fx : 1.f-fx);
        int ci = (dz ? z1 : z0)*256 + (dy ? y1 : y0)*16 + (dx ? x1 : x0);
        const float4* vp = (const float4*)(base + (size_t)ci*CSn);
        #pragma unroll
        for (int j = 0; j < 4; ++j) {
            float4 vv = vp[j];
            acc[j].x += wt*vv.x; acc[j].y += wt*vv.y;
            acc[j].z += wt*vv.z; acc[j].w += wt*vv.w;
        }
    }
    // write group-major up image
    float4* og = (float4*)&g_upg[((size_t)(b*Gn + g)*Pn + p)*CGn];
    #pragma unroll
    for (int j = 0; j < 4; ++j) og[j] = acc[j];

    __syncthreads();

    // cat hi/lo: dst channels g*16..g*16+15 and up channels 128+g*16..+15
    const float* af = (const float*)acc;
    uint32_t dh[8], dl[8], uh[8], ul[8];
    #pragma unroll
    for (int j = 0; j < 8; ++j) {
        float f0 = cat_s[(g*16 + 2*j    )*33 + v];
        float f1 = cat_s[(g*16 + 2*j + 1)*33 + v];
        uint32_t hd = cvtbf2(f1, f0);
        dh[j] = hd;
        dl[j] = cvtbf2(f1 - __uint_as_float(hd & 0xffff0000u),
                       f0 - __uint_as_float(hd << 16));
        float u0 = 2.0f*af[2*j], u1 = 2.0f*af[2*j+1];
        uint32_t hu = cvtbf2(u1, u0);
        uh[j] = hu;
        ul[j] = cvtbf2(u1 - __uint_as_float(hu & 0xffff0000u),
                       u0 - __uint_as_float(hu << 16));
    }
    size_t cb = ((size_t)b*Pn + p)*256 + g*16;
    uint4* ch = (uint4*)&g_cath[cb];
    uint4* cl = (uint4*)&g_catl[cb];
    ch[0] = make_uint4(dh[0],dh[1],dh[2],dh[3]); ch[1] = make_uint4(dh[4],dh[5],dh[6],dh[7]);
    cl[0] = make_uint4(dl[0],dl[1],dl[2],dl[3]); cl[1] = make_uint4(dl[4],dl[5],dl[6],dl[7]);
    uint4* chu = (uint4*)&g_cath[cb + 128];
    uint4* clu = (uint4*)&g_catl[cb + 128];
    chu[0] = make_uint4(uh[0],uh[1],uh[2],uh[3]); chu[1] = make_uint4(uh[4],uh[5],uh[6],uh[7]);
    clu[0] = make_uint4(ul[0],ul[1],ul[2],ul[3]); clu[1] = make_uint4(ul[4],ul[5],ul[6],ul[7]);
}

// -------- offset GEMM on tensor cores, dual N-tile, 4Mx2N warp grid ----------
__global__ void __launch_bounds__(256) k_offmma() {
    __shared__ __align__(16) uint8_t sW[2][WTILE];      // 20KB
    __shared__ __align__(16) uint8_t sS[2][2][STILE];   // 20KB

    int blk = blockIdx.x;               // Bn*MTILES*128 = 1536
    int b  = blk / (MTILES*128);
    int r  = blk % (MTILES*128);
    int mt = r / 128;
    int p0 = (r % 128) * 128;
    int t  = threadIdx.x;
    int w  = t >> 5, l = t & 31;
    int wm = w & 3, wn = w >> 2;        // warp = 32 o x 64 p

    float dacc[2][8][4];
    #pragma unroll
    for (int mi = 0; mi < 2; ++mi)
        #pragma unroll
        for (int n = 0; n < 8; ++n)
            #pragma unroll
            for (int j = 0; j < 4; ++j) dacc[mi][n][j] = 0.f;

    int btile = t >> 7, brow = (t & 127) >> 1, bpart = t & 1;
    const __nv_bfloat16* catsrc = (bpart ? g_catl : g_cath)
                                + ((size_t)b*Pn + p0 + btile*64 + brow)*256;

    auto domma = [&](int buf) {
        uint32_t sWb = (uint32_t)__cvta_generic_to_shared(&sW[buf][0]);
        uint32_t ah[2][4], al[2][4];
        #pragma unroll
        for (int mi = 0; mi < 2; ++mi) {
            uint32_t aaddr = sWb + (wm*32 + mi*16 + (l & 15))*WROW + (l >> 4)*16;
            ldsm4(ah[mi], aaddr);
            ldsm4(al[mi], aaddr + 32);
        }
        uint32_t br = 8*(l >> 4) + (l & 7);
        uint32_t bc = ((l >> 3) & 1)*16;
        uint32_t sSb = (uint32_t)__cvta_generic_to_shared(&sS[buf][wn][0]);
        #pragma unroll
        for (int nc = 0; nc < 4; ++nc) {
            uint32_t baddr = sSb + (nc*16 + br)*WROW + bc;
            uint32_t bh[4], bl[4];
            ldsm4(bh, baddr);
            ldsm4(bl, baddr + 32);
            #pragma unroll
            for (int mi = 0; mi < 2; ++mi) {
                mma16816(dacc[mi][2*nc  ], ah[mi], bh[0], bh[1]);
                mma16816(dacc[mi][2*nc  ], ah[mi], bl[0], bl[1]);
                mma16816(dacc[mi][2*nc  ], al[mi], bh[0], bh[1]);
                mma16816(dacc[mi][2*nc+1], ah[mi], bh[2], bh[3]);
                mma16816(dacc[mi][2*nc+1], ah[mi], bl[2], bl[3]);
                mma16816(dacc[mi][2*nc+1], al[mi], bh[2], bh[3]);
            }
        }
    };

    // prologue: chunk 0
    {
        const uint4* srcW = (const uint4*)(g_wosplit + (size_t)(mt*16)*WTILE);
        uint4* dW = (uint4*)sW[0];
        dW[t] = srcW[t];
        dW[t + 256] = srcW[t + 256];
        if (t < 128) dW[t + 512] = srcW[t + 512];
        const uint4* s = (const uint4*)catsrc;
        uint4* dr = (uint4*)(sS[0][btile] + brow*WROW + bpart*32);
        dr[0] = s[0]; dr[1] = s[1];
    }
    __syncthreads();

    for (int kc = 0; kc < 16; ++kc) {
        int cur = kc & 1;
        bool more = (kc + 1 < 16);
        uint4 wa, wb, wc2, b0, b1;
        if (more) {
            const uint4* srcW = (const uint4*)(g_wosplit + (size_t)(mt*16 + kc + 1)*WTILE);
            wa = srcW[t];
            wb = srcW[t + 256];
            if (t < 128) wc2 = srcW[t + 512];
            const uint4* s = (const uint4*)(catsrc + (kc + 1)*16);
            b0 = s[0]; b1 = s[1];
        }
        domma(cur);
        if (more) {
            int nb = cur ^ 1;
            uint4* dW = (uint4*)sW[nb];
            dW[t] = wa;
            dW[t + 256] = wb;
            if (t < 128) dW[t + 512] = wc2;
            uint4* dr = (uint4*)(sS[nb][btile] + brow*WROW + bpart*32);
            dr[0] = b0; dr[1] = b1;
        }
        __syncthreads();
    }

    // epilogue: write g_off (fp32, guarded o<648)
    int g = l >> 2, tq = l & 3;
    int pcb = p0 + wn*64 + 2*tq;
    #pragma unroll
    for (int mi = 0; mi < 2; ++mi) {
        int o0 = mt*128 + wm*32 + mi*16 + g;
        int o1 = o0 + 8;
        size_t base0 = ((size_t)b*NOFF + o0)*Pn + pcb;
        size_t base1 = ((size_t)b*NOFF + o1)*Pn + pcb;
        #pragma unroll
        for (int n = 0; n < 8; ++n) {
            if (o0 < NOFF)
                *(float2*)&g_off[base0 + n*8] = make_float2(dacc[mi][n][0], dacc[mi][n][1]);
            if (o1 < NOFF)
                *(float2*)&g_off[base1 + n*8] = make_float2(dacc[mi][n][2], dacc[mi][n][3]);
        }
    }
}

// -------- fused deformable sampling + bf16-split tensor GEMM + ReLU ---------
// block: 64 voxels, 256 threads, 2 CTAs/SM; 6-buffer ring, 3 taps per barrier.
__global__ void __launch_bounds__(256, 2) k_dcn(float* __restrict__ out) {
    extern __shared__ __align__(16) uint8_t dyn[];
    uint8_t* sW = dyn;                  // 6 x WTILE
    uint8_t* sS = dyn + 6*WTILE;        // 6 x STILE
    const uint32_t sWu = (uint32_t)__cvta_generic_to_shared(sW);

    int blk = blockIdx.x;               // Bn*(Pn/64) = 512
    int b  = blk >> 8;
    int p0 = (blk & 255) * 64;
    int t  = threadIdx.x;
    int w  = t >> 5, l = t & 31;
    int vv = t >> 2, q = t & 3;

    float dacc[8][4];
    #pragma unroll
    for (int n = 0; n < 8; ++n)
        #pragma unroll
        for (int j = 0; j < 4; ++j) dacc[n][j] = 0.f;

    const size_t offB = (size_t)b * NOFF * Pn;
    const float* upg4 = g_upg + (size_t)(b*Gn)*Pn*CGn + q*4;

    int p = p0 + vv;
    int dg = p >> 10, hg = (p >> 5) & 31, wg = p & 31;

    auto loadoffs = [&](int kk, float& z, float& y, float& x) {
        int g = kk / K3n, k = kk % K3n;
        int kz = k/9 - 1, ky = (k/3)%3 - 1, kx = k%3 - 1;
        size_t ob = offB + (size_t)(g*K3n + k)*3*Pn + p;
        z = dg + kz + g_off[ob];
        y = hg + ky + g_off[ob + Pn];
        x = wg + kx + g_off[ob + 2*Pn];
    };

    auto wasync = [&](int kk, int buf) {
        const char* src = (const char*)(g_wsplit + (size_t)kk*WTILE);
        uint32_t dst = sWu + buf*WTILE;
        cpasync16(dst + t*16,         src + t*16);
        cpasync16(dst + (t+256)*16,   src + (t+256)*16);
        if (t < 128) cpasync16(dst + (t+512)*16, src + (t+512)*16);
    };

    auto gather = [&](int kk, float z, float y, float x, int buf) {
        int g = kk / K3n;
        const float* upg = upg4 + (size_t)g*Pn*CGn;

        float z0f = floorf(z), y0f = floorf(y), x0f = floorf(x);
        float fz = z - z0f, fy = y - y0f, fx = x - x0f;
        int z0 = (int)z0f, y0 = (int)y0f, x0 = (int)x0f;

        float wz0 = (z0   >= 0 && z0   < DDn) ? 1.f - fz : 0.f;
        float wz1 = (z0+1 >= 0 && z0+1 < DDn) ? fz       : 0.f;
        float wy0 = (y0   >= 0 && y0   < DHn) ? 1.f - fy : 0.f;
        float wy1 = (y0+1 >= 0 && y0+1 < DHn) ? fy       : 0.f;
        float wx0 = (x0   >= 0 && x0   < DWn) ? 1.f - fx : 0.f;
        float wx1 = (x0+1 >= 0 && x0+1 < DWn) ? fx       : 0.f;
        int zi0 = min(max(z0,   0), DDn-1) << 10;
        int zi1 = min(max(z0+1, 0), DDn-1) << 10;
        int yi0 = min(max(y0,   0), DHn-1) << 5;
        int yi1 = min(max(y0+1, 0), DHn-1) << 5;
        int xi0 = min(max(x0,   0), DWn-1);
        int xi1 = min(max(x0+1, 0), DWn-1);
        float w00 = wz0*wy0, w01 = wz0*wy1, w10 = wz1*wy0, w11 = wz1*wy1;
        int   i00 = zi0+yi0, i01 = zi0+yi1, i10 = zi1+yi0, i11 = zi1+yi1;

        float4 sa = make_float4(0.f, 0.f, 0.f, 0.f);
        #pragma unroll
        for (int cnr = 0; cnr < 8; ++cnr) {
            float wzy = (cnr>>2) ? ((cnr>>1)&1 ? w11 : w10) : ((cnr>>1)&1 ? w01 : w00);
            int   izy = (cnr>>2) ? ((cnr>>1)&1 ? i11 : i10) : ((cnr>>1)&1 ? i01 : i00);
            float wt  = wzy * ((cnr&1) ? wx1 : wx0);
            int   ci  = izy + ((cnr&1) ? xi1 : xi0);
            float4 v = *(const float4*)(upg + (size_t)ci*CGn);
            sa.x += wt*v.x; sa.y += wt*v.y; sa.z += wt*v.z; sa.w += wt*v.w;
        }
        uint32_t h01 = cvtbf2(sa.y, sa.x);
        uint32_t h23 = cvtbf2(sa.w, sa.z);
        uint32_t l01 = cvtbf2(sa.y - __uint_as_float(h01 & 0xffff0000u),
                              sa.x - __uint_as_float(h01 << 16));
        uint32_t l23 = cvtbf2(sa.w - __uint_as_float(h23 & 0xffff0000u),
                              sa.z - __uint_as_float(h23 << 16));
        uint8_t* rowp = sS + buf*STILE + vv*WROW + q*8;
        *(uint2*)rowp        = make_uint2(h01, h23);
        *(uint2*)(rowp + 32) = make_uint2(l01, l23);
    };

    auto domma = [&](int buf) {
        uint32_t sWb = sWu + buf*WTILE;
        uint32_t sSb = (uint32_t)__cvta_generic_to_shared(sS + buf*STILE);
        uint32_t aaddr = sWb + (w*16 + (l & 15))*WROW + (l >> 4)*16;
        uint32_t ah[4], al[4];
        ldsm4(ah, aaddr);
        ldsm4(al, aaddr + 32);
        uint32_t brow = 8*(l >> 4) + (l & 7);
        uint32_t bcol = ((l >> 3) & 1)*16;
        #pragma unroll
        for (int nc = 0; nc < 4; ++nc) {
            uint32_t baddr = sSb + (nc*16 + brow)*WROW + bcol;
            uint32_t bh[4], bl[4];
            ldsm4(bh, baddr);
            ldsm4(bl, baddr + 32);
            mma16816(dacc[2*nc  ], ah, bh[0], bh[1]);
            mma16816(dacc[2*nc  ], ah, bl[0], bl[1]);
            mma16816(dacc[2*nc  ], al, bh[0], bh[1]);
            mma16816(dacc[2*nc+1], ah, bh[2], bh[3]);
            mma16816(dacc[2*nc+1], ah, bl[2], bl[3]);
            mma16816(dacc[2*nc+1], al, bh[2], bh[3]);
        }
    };

    float zo[3], yo[3], xo[3];          // prefetched offsets for next phase

    // ---- prologue: taps 0,1,2 ----
    {
        float za, ya, xa;
        wasync(0, 0); wasync(1, 1); wasync(2, 2);
        cpcommit();
        loadoffs(0, za, ya, xa); gather(0, za, ya, xa, 0);
        loadoffs(1, za, ya, xa); gather(1, za, ya, xa, 1);
        loadoffs(2, za, ya, xa); gather(2, za, ya, xa, 2);
        loadoffs(3, zo[0], yo[0], xo[0]);
        loadoffs(4, zo[1], yo[1], xo[1]);
        loadoffs(5, zo[2], yo[2], xo[2]);
        cpwait0();
    }
    __syncthreads();

    // ---- main loop: 3 taps per barrier, 6-buffer ring ----
    int cur = 0;
    for (int kk = 0; kk < NTAP; kk += 3) {
        int nxt = cur ^ 3;
        bool more = (kk + 3 < NTAP);
        if (more) {
            wasync(kk + 3, nxt);
            wasync(kk + 4, nxt + 1);
            wasync(kk + 5, nxt + 2);
            cpcommit();
        }

        domma(cur);
        domma(cur + 1);
        domma(cur + 2);

        if (more) {
            gather(kk + 3, zo[0], yo[0], xo[0], nxt);
            gather(kk + 4, zo[1], yo[1], xo[1], nxt + 1);
            gather(kk + 5, zo[2], yo[2], xo[2], nxt + 2);
            if (kk + 6 < NTAP) {
                loadoffs(kk + 6, zo[0], yo[0], xo[0]);
                loadoffs(kk + 7, zo[1], yo[1], xo[1]);
                loadoffs(kk + 8, zo[2], yo[2], xo[2]);
            }
            cpwait0();
        }
        __syncthreads();
        cur = nxt;
    }

    // ---- epilogue: ReLU + STG.64 ----
    int g = l >> 2, tq = l & 3;
    size_t base0 = ((size_t)b*CDn + w*16 + g)*Pn + p0 + 2*tq;
    size_t base1 = base0 + (size_t)8*Pn;
    #pragma unroll
    for (int n = 0; n < 8; ++n) {
        float2 v0 = make_float2(fmaxf(dacc[n][0], 0.f), fmaxf(dacc[n][1], 0.f));
        float2 v1 = make_float2(fmaxf(dacc[n][2], 0.f), fmaxf(dacc[n][3], 0.f));
        *(float2*)&out[base0 + n*8] = v0;
        *(float2*)&out[base1 + n*8] = v1;
    }
}

extern "C" void kernel_launch(void* const* d_in, const int* in_sizes, int n_in,
                              void* d_out, int out_size) {
    const float* src  = (const float*)d_in[0];   // feat_1x_src [2,128,8,16,16]
    const float* dst  = (const float*)d_in[1];   // feat_2x_dst [2,128,16,32,32]
    const float* woff = (const float*)d_in[2];   // w_offset [648,256]
    const float* wdcn = (const float*)d_in[3];   // w_dcn [128,128,3,3,3]
    float* out = (float*)d_out;

    cudaFuncSetAttribute(k_dcn, cudaFuncAttributeMaxDynamicSharedMemorySize,
                         DCN_SMEM);

    const int NPREP = Bn*SDn*SHn*SWn*CSn + NTAP*128*CGn + MTILES*128*256;
    k_prep   <<<(NPREP + 255)/256, 256>>>(src, woff, wdcn);
    k_up     <<<Bn*(Pn/32), 256>>>(dst);
    k_offmma <<<Bn*MTILES*128, 256>>>();
    k_dcn    <<<Bn*(Pn/64), 256, DCN_SMEM>>>(out);
}

// round 17
// speedup vs baseline: 1.3302x; 1.0155x over previous
#include <cuda_runtime.h>
#include <cuda_bf16.h>
#include <cstdint>

#define Bn 2
#define CSn 128
#define CDn 128
#define SDn 8
#define SHn 16
#define SWn 16
#define DDn 16
#define DHn 32
#define DWn 32
#define Pn  (DDn*DHn*DWn)      /* 16384 */
#define Gn 8
#define K3n 27
#define CGn 16                 /* CS/G */
#define NOFF (K3n*3*Gn)        /* 648 */
#define NTAP (Gn*K3n)          /* 216 */
#define WROW 80                /* padded row bytes of A/B smem tiles */
#define WTILE (128*WROW)       /* 10240 B per weight tile */
#define STILE (64*WROW)        /* 5120 B per sample tile */
#define MTILES 6               /* ceil(648/128) m-tiles for offset GEMM */
#define DCN_SMEM (6*WTILE + 6*STILE)   /* 92160 B */

typedef unsigned long long ull;

// ---------------- f32x2 / bf16 helpers ----------------------------------------
__device__ __forceinline__ ull ffma2(ull a, ull b, ull c) {
    ull d;
    asm("fma.rn.f32x2 %0, %1, %2, %3;" : "=l"(d) : "l"(a), "l"(b), "l"(c));
    return d;
}
__device__ __forceinline__ ull dup2(float s) {
    ull d;
    unsigned u = __float_as_uint(s);
    asm("mov.b64 %0, {%1, %1};" : "=l"(d) : "r"(u));
    return d;
}
__device__ __forceinline__ float lo32(ull v) {
    return __uint_as_float((unsigned)(v & 0xffffffffull));
}
__device__ __forceinline__ float hi32(ull v) {
    return __uint_as_float((unsigned)(v >> 32));
}
__device__ __forceinline__ uint32_t cvtbf2(float hi, float lo) { // {hi,lo} packed
    uint32_t r;
    asm("cvt.rn.bf16x2.f32 %0, %1, %2;" : "=r"(r) : "f"(hi), "f"(lo));
    return r;
}

// ---------------- cp.async helpers --------------------------------------------
__device__ __forceinline__ void cpasync16(uint32_t saddr, const void* g) {
    asm volatile("cp.async.cg.shared.global [%0], [%1], 16;"
                 :: "r"(saddr), "l"(g));
}
__device__ __forceinline__ void cpcommit() {
    asm volatile("cp.async.commit_group;");
}
__device__ __forceinline__ void cpwait0() {
    asm volatile("cp.async.wait_group 0;" ::: "memory");
}

// ---------------- tensor-core helpers ---------------------------------------
__device__ __forceinline__ void ldsm4(uint32_t* r, uint32_t addr) {
    asm volatile("ldmatrix.sync.aligned.m8n8.x4.shared.b16 {%0,%1,%2,%3},[%4];"
        : "=r"(r[0]), "=r"(r[1]), "=r"(r[2]), "=r"(r[3]) : "r"(addr));
}
__device__ __forceinline__ void mma16816(float* d, const uint32_t* a,
                                         uint32_t b0, uint32_t b1) {
    asm volatile(
        "mma.sync.aligned.m16n8k16.row.col.f32.bf16.bf16.f32 "
        "{%0,%1,%2,%3},{%4,%5,%6,%7},{%8,%9},{%0,%1,%2,%3};"
        : "+f"(d[0]), "+f"(d[1]), "+f"(d[2]), "+f"(d[3])
        : "r"(a[0]), "r"(a[1]), "r"(a[2]), "r"(a[3]), "r"(b0), "r"(b1));
}

// -------- device scratch ----------------------------------------------------
__device__ float g_src_cl[Bn*SDn*SHn*SWn*CSn];   // [b][z][y][x][c]
__device__ float g_upg[(size_t)Bn*Gn*Pn*CGn];    // [b][g][p][cg]  (group-major)
__device__ float g_off[Bn*NOFF*Pn];              // [b][o][p]
__device__ char4 g_tap[NTAP];                    // (kz,ky,kx,g) per tap
__device__ __align__(16) uint8_t g_wsplit[(size_t)NTAP*WTILE];       // dcn W hi/lo
__device__ __align__(16) uint8_t g_wosplit[(size_t)MTILES*16*WTILE]; // offset W hi/lo
__device__ __align__(16) __nv_bfloat16 g_cath[(size_t)Bn*Pn*256];    // cat hi [b][p][c]
__device__ __align__(16) __nv_bfloat16 g_catl[(size_t)Bn*Pn*256];    // cat lo

// -------- prep: transposes + bf16 weight splits + tap table -------------------
__global__ void k_prep(const float* __restrict__ src,
                       const float* __restrict__ woff,
                       const float* __restrict__ wdcn) {
    int i = blockIdx.x * blockDim.x + threadIdx.x;
    const int N1 = Bn*SDn*SHn*SWn*CSn;    // 524288
    const int N3 = NTAP*128*CGn;          // 442368
    const int N4 = MTILES*128*256;        // 196608 (768 o x 256 c)
    if (i < N1) {
        int c = i % CSn;
        int s = (i / CSn) % (SDn*SHn*SWn);
        int b = i / (CSn*SDn*SHn*SWn);
        g_src_cl[i] = src[(b*CSn + c)*(SDn*SHn*SWn) + s];
    } else if (i < N1 + N3) {
        int j = i - N1;
        int cg = j % CGn;
        int o  = (j / CGn) % 128;
        int kk = j / (CGn*128);
        int g = kk / K3n, k = kk % K3n;
        float wv = wdcn[((o*CSn) + g*CGn + cg)*K3n + k];
        __nv_bfloat16 hb = __float2bfloat16(wv);
        __nv_bfloat16 lb = __float2bfloat16(wv - __bfloat162float(hb));
        uint8_t* row = g_wsplit + (size_t)kk*WTILE + o*WROW;
        *(__nv_bfloat16*)(row + cg*2)      = hb;
        *(__nv_bfloat16*)(row + 32 + cg*2) = lb;
    } else if (i < N1 + N3 + N4) {
        int j = i - N1 - N3;
        int c = j % 256;
        int o = j / 256;                  // 0..767 (padded)
        float wv = (o < NOFF) ? woff[o*256 + c] : 0.f;
        __nv_bfloat16 hb = __float2bfloat16(wv);
        __nv_bfloat16 lb = __float2bfloat16(wv - __bfloat162float(hb));
        int mt = o >> 7, kc = c >> 4;
        uint8_t* row = g_wosplit + (size_t)(mt*16 + kc)*WTILE + (o & 127)*WROW;
        *(__nv_bfloat16*)(row + (c & 15)*2)      = hb;
        *(__nv_bfloat16*)(row + 32 + (c & 15)*2) = lb;
    } else if (i < N1 + N3 + N4 + NTAP) {
        int kk = i - N1 - N3 - N4;
        int g = kk / K3n, k = kk % K3n;
        g_tap[kk] = make_char4((char)(k/9 - 1), (char)((k/3)%3 - 1),
                               (char)(k%3 - 1), (char)g);
    }
}

// -------- fused upsample + cat: writes g_upg, g_cath, g_catl ------------------
__global__ void __launch_bounds__(256) k_up(const float* __restrict__ dst) {
    __shared__ float cat_s[128*33];     // dst staging [c][v], padded
    int blk = blockIdx.x;               // Bn*(Pn/32) = 1024
    int b  = blk / (Pn/32);
    int p0 = (blk % (Pn/32)) * 32;
    int t  = threadIdx.x;
    int v  = t & 31, g = t >> 5;

    for (int i = t; i < 128*32; i += 256) {
        int c = i >> 5, vv = i & 31;
        cat_s[c*33 + vv] = dst[((size_t)b*CDn + c)*Pn + p0 + vv];
    }

    int p = p0 + v;
    int d = p >> 10, h = (p >> 5) & 31, w = p & 31;
    float zc = d*0.5f - 0.25f, yc = h*0.5f - 0.25f, xc = w*0.5f - 0.25f;
    int zf = (int)floorf(zc), yf = (int)floorf(yc), xf = (int)floorf(xc);
    float fz = zc - zf, fy = yc - yf, fx = xc - xf;
    int z0 = min(max(zf,     0), SDn-1), z1 = min(max(zf + 1, 0), SDn-1);
    int y0 = min(max(yf,     0), SHn-1), y1 = min(max(yf + 1, 0), SHn-1);
    int x0 = min(max(xf,     0), SWn-1), x1 = min(max(xf + 1, 0), SWn-1);

    const float* base = g_src_cl + (size_t)b*(SDn*SHn*SWn)*CSn + g*CGn;
    float4 acc[4];
    #pragma unroll
    for (int j = 0; j < 4; ++j) acc[j] = make_float4(0.f, 0.f, 0.f, 0.f);
    #pragma unroll
    for (int cnr = 0; cnr < 8; ++cnr) {
        int dz = cnr>>2, dy = (cnr>>1)&1, dx = cnr&1;
        float wt = (dz ? fz : 1.f-fz) * (dy ? fy : 1.f-fy) * (dx ? fx : 1.f-fx);
        int ci = (dz ? z1 : z0)*256 + (dy ? y1 : y0)*16 + (dx ? x1 : x0);
        const float4* vp = (const float4*)(base + (size_t)ci*CSn);
        #pragma unroll
        for (int j = 0; j < 4; ++j) {
            float4 vv = vp[j];
            acc[j].x += wt*vv.x; acc[j].y += wt*vv.y;
            acc[j].z += wt*vv.z; acc[j].w += wt*vv.w;
        }
    }
    float4* og = (float4*)&g_upg[((size_t)(b*Gn + g)*Pn + p)*CGn];
    #pragma unroll
    for (int j = 0; j < 4; ++j) og[j] = acc[j];

    __syncthreads();

    const float* af = (const float*)acc;
    uint32_t dh[8], dl[8], uh[8], ul[8];
    #pragma unroll
    for (int j = 0; j < 8; ++j) {
        float f0 = cat_s[(g*16 + 2*j    )*33 + v];
        float f1 = cat_s[(g*16 + 2*j + 1)*33 + v];
        uint32_t hd = cvtbf2(f1, f0);
        dh[j] = hd;
        dl[j] = cvtbf2(f1 - __uint_as_float(hd & 0xffff0000u),
                       f0 - __uint_as_float(hd << 16));
        float u0 = 2.0f*af[2*j], u1 = 2.0f*af[2*j+1];
        uint32_t hu = cvtbf2(u1, u0);
        uh[j] = hu;
        ul[j] = cvtbf2(u1 - __uint_as_float(hu & 0xffff0000u),
                       u0 - __uint_as_float(hu << 16));
    }
    size_t cb = ((size_t)b*Pn + p)*256 + g*16;
    uint4* ch = (uint4*)&g_cath[cb];
    uint4* cl = (uint4*)&g_catl[cb];
    ch[0] = make_uint4(dh[0],dh[1],dh[2],dh[3]); ch[1] = make_uint4(dh[4],dh[5],dh[6],dh[7]);
    cl[0] = make_uint4(dl[0],dl[1],dl[2],dl[3]); cl[1] = make_uint4(dl[4],dl[5],dl[6],dl[7]);
    uint4* chu = (uint4*)&g_cath[cb + 128];
    uint4* clu = (uint4*)&g_catl[cb + 128];
    chu[0] = make_uint4(uh[0],uh[1],uh[2],uh[3]); chu[1] = make_uint4(uh[4],uh[5],uh[6],uh[7]);
    clu[0] = make_uint4(ul[0],ul[1],ul[2],ul[3]); clu[1] = make_uint4(ul[4],ul[5],ul[6],ul[7]);
}

// -------- offset GEMM on tensor cores, dual N-tile, 4Mx2N warp grid ----------
__global__ void __launch_bounds__(256) k_offmma() {
    __shared__ __align__(16) uint8_t sW[2][WTILE];      // 20KB
    __shared__ __align__(16) uint8_t sS[2][2][STILE];   // 20KB

    int blk = blockIdx.x;               // Bn*MTILES*128 = 1536
    int b  = blk / (MTILES*128);
    int r  = blk % (MTILES*128);
    int mt = r / 128;
    int p0 = (r % 128) * 128;
    int t  = threadIdx.x;
    int w  = t >> 5, l = t & 31;
    int wm = w & 3, wn = w >> 2;        // warp = 32 o x 64 p

    float dacc[2][8][4];
    #pragma unroll
    for (int mi = 0; mi < 2; ++mi)
        #pragma unroll
        for (int n = 0; n < 8; ++n)
            #pragma unroll
            for (int j = 0; j < 4; ++j) dacc[mi][n][j] = 0.f;

    int btile = t >> 7, brow = (t & 127) >> 1, bpart = t & 1;
    const __nv_bfloat16* catsrc = (bpart ? g_catl : g_cath)
                                + ((size_t)b*Pn + p0 + btile*64 + brow)*256;

    auto domma = [&](int buf) {
        uint32_t sWb = (uint32_t)__cvta_generic_to_shared(&sW[buf][0]);
        uint32_t ah[2][4], al[2][4];
        #pragma unroll
        for (int mi = 0; mi < 2; ++mi) {
            uint32_t aaddr = sWb + (wm*32 + mi*16 + (l & 15))*WROW + (l >> 4)*16;
            ldsm4(ah[mi], aaddr);
            ldsm4(al[mi], aaddr + 32);
        }
        uint32_t br = 8*(l >> 4) + (l & 7);
        uint32_t bc = ((l >> 3) & 1)*16;
        uint32_t sSb = (uint32_t)__cvta_generic_to_shared(&sS[buf][wn][0]);
        #pragma unroll
        for (int nc = 0; nc < 4; ++nc) {
            uint32_t baddr = sSb + (nc*16 + br)*WROW + bc;
            uint32_t bh[4], bl[4];
            ldsm4(bh, baddr);
            ldsm4(bl, baddr + 32);
            #pragma unroll
            for (int mi = 0; mi < 2; ++mi) {
                mma16816(dacc[mi][2*nc  ], ah[mi], bh[0], bh[1]);
                mma16816(dacc[mi][2*nc  ], ah[mi], bl[0], bl[1]);
                mma16816(dacc[mi][2*nc  ], al[mi], bh[0], bh[1]);
                mma16816(dacc[mi][2*nc+1], ah[mi], bh[2], bh[3]);
                mma16816(dacc[mi][2*nc+1], ah[mi], bl[2], bl[3]);
                mma16816(dacc[mi][2*nc+1], al[mi], bh[2], bh[3]);
            }
        }
    };

    // prologue: chunk 0
    {
        const uint4* srcW = (const uint4*)(g_wosplit + (size_t)(mt*16)*WTILE);
        uint4* dW = (uint4*)sW[0];
        dW[t] = srcW[t];
        dW[t + 256] = srcW[t + 256];
        if (t < 128) dW[t + 512] = srcW[t + 512];
        const uint4* s = (const uint4*)catsrc;
        uint4* dr = (uint4*)(sS[0][btile] + brow*WROW + bpart*32);
        dr[0] = s[0]; dr[1] = s[1];
    }
    __syncthreads();

    for (int kc = 0; kc < 16; ++kc) {
        int cur = kc & 1;
        bool more = (kc + 1 < 16);
        uint4 wa, wb, wc2, b0, b1;
        if (more) {
            const uint4* srcW = (const uint4*)(g_wosplit + (size_t)(mt*16 + kc + 1)*WTILE);
            wa = srcW[t];
            wb = srcW[t + 256];
            if (t < 128) wc2 = srcW[t + 512];
            const uint4* s = (const uint4*)(catsrc + (kc + 1)*16);
            b0 = s[0]; b1 = s[1];
        }
        domma(cur);
        if (more) {
            int nb = cur ^ 1;
            uint4* dW = (uint4*)sW[nb];
            dW[t] = wa;
            dW[t + 256] = wb;
            if (t < 128) dW[t + 512] = wc2;
            uint4* dr = (uint4*)(sS[nb][btile] + brow*WROW + bpart*32);
            dr[0] = b0; dr[1] = b1;
        }
        __syncthreads();
    }

    // epilogue: write g_off (fp32, guarded o<648)
    int g = l >> 2, tq = l & 3;
    int pcb = p0 + wn*64 + 2*tq;
    #pragma unroll
    for (int mi = 0; mi < 2; ++mi) {
        int o0 = mt*128 + wm*32 + mi*16 + g;
        int o1 = o0 + 8;
        size_t base0 = ((size_t)b*NOFF + o0)*Pn + pcb;
        size_t base1 = ((size_t)b*NOFF + o1)*Pn + pcb;
        #pragma unroll
        for (int n = 0; n < 8; ++n) {
            if (o0 < NOFF)
                *(float2*)&g_off[base0 + n*8] = make_float2(dacc[mi][n][0], dacc[mi][n][1]);
            if (o1 < NOFF)
                *(float2*)&g_off[base1 + n*8] = make_float2(dacc[mi][n][2], dacc[mi][n][3]);
        }
    }
}

// -------- fused deformable sampling + bf16-split tensor GEMM + ReLU ---------
// block: 64 voxels, 256 threads, 2 CTAs/SM; 6-buffer ring, 3 taps per barrier.
// R17: delta-based corner addressing, f32x2 gather accum, tap table,
//      running offset pointer.
__global__ void __launch_bounds__(256, 2) k_dcn(float* __restrict__ out) {
    extern __shared__ __align__(16) uint8_t dyn[];
    uint8_t* sW = dyn;                  // 6 x WTILE
    uint8_t* sS = dyn + 6*WTILE;        // 6 x STILE
    const uint32_t sWu = (uint32_t)__cvta_generic_to_shared(sW);

    int blk = blockIdx.x;               // Bn*(Pn/64) = 512
    int b  = blk >> 8;
    int p0 = (blk & 255) * 64;
    int t  = threadIdx.x;
    int w  = t >> 5, l = t & 31;
    int vv = t >> 2, q = t & 3;

    float dacc[8][4];
    #pragma unroll
    for (int n = 0; n < 8; ++n)
        #pragma unroll
        for (int j = 0; j < 4; ++j) dacc[n][j] = 0.f;

    const float* upg4 = g_upg + (size_t)(b*Gn)*Pn*CGn + q*4;

    int p = p0 + vv;
    int dg = p >> 10, hg = (p >> 5) & 31, wg = p & 31;
    const float* offp = g_off + (size_t)b*NOFF*Pn + p;   // tap-0 base

    // offsets via tap table + precomputed base pointer (no per-tap idx muls)
    auto loadoffs = [&](const float* ob, int kk, float& z, float& y, float& x,
                        int& gg) {
        char4 tk = g_tap[kk];
        z = dg + tk.x + ob[0];
        y = hg + tk.y + ob[Pn];
        x = wg + tk.z + ob[2*Pn];
        gg = tk.w;
    };

    auto wasync = [&](int kk, int buf) {
        const char* src = (const char*)(g_wsplit + (size_t)kk*WTILE);
        uint32_t dst = sWu + buf*WTILE;
        cpasync16(dst + t*16,         src + t*16);
        cpasync16(dst + (t+256)*16,   src + (t+256)*16);
        if (t < 128) cpasync16(dst + (t+512)*16, src + (t+512)*16);
    };

    // gather: delta-addressed corners, f32x2 accumulation (same corner order)
    auto gather = [&](int gg, float z, float y, float x, int buf) {
        const float* upg = upg4 + (size_t)gg*Pn*CGn;

        float z0f = floorf(z), y0f = floorf(y), x0f = floorf(x);
        float fz = z - z0f, fy = y - y0f, fx = x - x0f;
        int z0 = (int)z0f, y0 = (int)y0f, x0 = (int)x0f;

        float wz0 = (z0   >= 0 && z0   < DDn) ? 1.f - fz : 0.f;
        float wz1 = (z0+1 >= 0 && z0+1 < DDn) ? fz       : 0.f;
        float wy0 = (y0   >= 0 && y0   < DHn) ? 1.f - fy : 0.f;
        float wy1 = (y0+1 >= 0 && y0+1 < DHn) ? fy       : 0.f;
        float wx0 = (x0   >= 0 && x0   < DWn) ? 1.f - fx : 0.f;
        float wx1 = (x0+1 >= 0 && x0+1 < DWn) ? fx       : 0.f;
        int zi0 = min(max(z0,   0), DDn-1) << 10;
        int zi1 = min(max(z0+1, 0), DDn-1) << 10;
        int yi0 = min(max(y0,   0), DHn-1) << 5;
        int yi1 = min(max(y0+1, 0), DHn-1) << 5;
        int xi0 = min(max(x0,   0), DWn-1);
        int xi1 = min(max(x0+1, 0), DWn-1);
        float w00 = wz0*wy0, w01 = wz0*wy1, w10 = wz1*wy0, w11 = wz1*wy1;

        const char* pb = (const char*)upg + (size_t)(zi0 + yi0 + xi0)*(CGn*4);
        int dX = (xi1 - xi0)*(CGn*4);
        int dY = (yi1 - yi0)*(CGn*4);
        int dZ = (zi1 - zi0)*(CGn*4);

        ulonglong2 u0 = *(const ulonglong2*)(pb);
        ulonglong2 u1 = *(const ulonglong2*)(pb + dX);
        ulonglong2 u2 = *(const ulonglong2*)(pb + dY);
        ulonglong2 u3 = *(const ulonglong2*)(pb + dY + dX);
        ulonglong2 u4 = *(const ulonglong2*)(pb + dZ);
        ulonglong2 u5 = *(const ulonglong2*)(pb + dZ + dX);
        ulonglong2 u6 = *(const ulonglong2*)(pb + dZ + dY);
        ulonglong2 u7 = *(const ulonglong2*)(pb + dZ + dY + dX);

        ull a0 = 0ull, a1 = 0ull, wd;
        wd = dup2(w00*wx0); a0 = ffma2(u0.x, wd, a0); a1 = ffma2(u0.y, wd, a1);
        wd = dup2(w00*wx1); a0 = ffma2(u1.x, wd, a0); a1 = ffma2(u1.y, wd, a1);
        wd = dup2(w01*wx0); a0 = ffma2(u2.x, wd, a0); a1 = ffma2(u2.y, wd, a1);
        wd = dup2(w01*wx1); a0 = ffma2(u3.x, wd, a0); a1 = ffma2(u3.y, wd, a1);
        wd = dup2(w10*wx0); a0 = ffma2(u4.x, wd, a0); a1 = ffma2(u4.y, wd, a1);
        wd = dup2(w10*wx1); a0 = ffma2(u5.x, wd, a0); a1 = ffma2(u5.y, wd, a1);
        wd = dup2(w11*wx0); a0 = ffma2(u6.x, wd, a0); a1 = ffma2(u6.y, wd, a1);
        wd = dup2(w11*wx1); a0 = ffma2(u7.x, wd, a0); a1 = ffma2(u7.y, wd, a1);

        float s0 = lo32(a0), s1 = hi32(a0), s2 = lo32(a1), s3 = hi32(a1);
        uint32_t h01 = cvtbf2(s1, s0);
        uint32_t h23 = cvtbf2(s3, s2);
        uint32_t l01 = cvtbf2(s1 - __uint_as_float(h01 & 0xffff0000u),
                              s0 - __uint_as_float(h01 << 16));
        uint32_t l23 = cvtbf2(s3 - __uint_as_float(h23 & 0xffff0000u),
                              s2 - __uint_as_float(h23 << 16));
        uint8_t* rowp = sS + buf*STILE + vv*WROW + q*8;
        *(uint2*)rowp        = make_uint2(h01, h23);
        *(uint2*)(rowp + 32) = make_uint2(l01, l23);
    };

    auto domma = [&](int buf) {
        uint32_t sWb = sWu + buf*WTILE;
        uint32_t sSb = (uint32_t)__cvta_generic_to_shared(sS + buf*STILE);
        uint32_t aaddr = sWb + (w*16 + (l & 15))*WROW + (l >> 4)*16;
        uint32_t ah[4], al[4];
        ldsm4(ah, aaddr);
        ldsm4(al, aaddr + 32);
        uint32_t brow = 8*(l >> 4) + (l & 7);
        uint32_t bcol = ((l >> 3) & 1)*16;
        #pragma unroll
        for (int nc = 0; nc < 4; ++nc) {
            uint32_t baddr = sSb + (nc*16 + brow)*WROW + bcol;
            uint32_t bh[4], bl[4];
            ldsm4(bh, baddr);
            ldsm4(bl, baddr + 32);
            mma16816(dacc[2*nc  ], ah, bh[0], bh[1]);
            mma16816(dacc[2*nc  ], ah, bl[0], bl[1]);
            mma16816(dacc[2*nc  ], al, bh[0], bh[1]);
            mma16816(dacc[2*nc+1], ah, bh[2], bh[3]);
            mma16816(dacc[2*nc+1], ah, bl[2], bl[3]);
            mma16816(dacc[2*nc+1], al, bh[2], bh[3]);
        }
    };

    float zo[3], yo[3], xo[3];
    int go[3];

    // ---- prologue: taps 0,1,2 ----
    {
        float za, ya, xa; int ga;
        wasync(0, 0); wasync(1, 1); wasync(2, 2);
        cpcommit();
        loadoffs(offp,           0, za, ya, xa, ga); gather(ga, za, ya, xa, 0);
        loadoffs(offp + 3*Pn,    1, za, ya, xa, ga); gather(ga, za, ya, xa, 1);
        loadoffs(offp + 6*Pn,    2, za, ya, xa, ga); gather(ga, za, ya, xa, 2);
        loadoffs(offp + 9*Pn,    3, zo[0], yo[0], xo[0], go[0]);
        loadoffs(offp + 12*Pn,   4, zo[1], yo[1], xo[1], go[1]);
        loadoffs(offp + 15*Pn,   5, zo[2], yo[2], xo[2], go[2]);
        cpwait0();
    }
    __syncthreads();

    // ---- main loop: 3 taps per barrier, 6-buffer ring ----
    int cur = 0;
    for (int kk = 0; kk < NTAP; kk += 3) {
        int nxt = cur ^ 3;
        bool more = (kk + 3 < NTAP);
        if (more) {
            wasync(kk + 3, nxt);
            wasync(kk + 4, nxt + 1);
            wasync(kk + 5, nxt + 2);
            cpcommit();
        }

        domma(cur);
        domma(cur + 1);
        domma(cur + 2);

        if (more) {
            gather(go[0], zo[0], yo[0], xo[0], nxt);
            gather(go[1], zo[1], yo[1], xo[1], nxt + 1);
            gather(go[2], zo[2], yo[2], xo[2], nxt + 2);
            if (kk + 6 < NTAP) {
                const float* ph = offp + (size_t)(kk + 6)*3*Pn;
                loadoffs(ph,         kk + 6, zo[0], yo[0], xo[0], go[0]);
                loadoffs(ph + 3*Pn,  kk + 7, zo[1], yo[1], xo[1], go[1]);
                loadoffs(ph + 6*Pn,  kk + 8, zo[2], yo[2], xo[2], go[2]);
            }
            cpwait0();
        }
        __syncthreads();
        cur = nxt;
    }

    // ---- epilogue: ReLU + STG.64 ----
    int g = l >> 2, tq = l & 3;
    size_t base0 = ((size_t)b*CDn + w*16 + g)*Pn + p0 + 2*tq;
    size_t base1 = base0 + (size_t)8*Pn;
    #pragma unroll
    for (int n = 0; n < 8; ++n) {
        float2 v0 = make_float2(fmaxf(dacc[n][0], 0.f), fmaxf(dacc[n][1], 0.f));
        float2 v1 = make_float2(fmaxf(dacc[n][2], 0.f), fmaxf(dacc[n][3], 0.f));
        *(float2*)&out[base0 + n*8] = v0;
        *(float2*)&out[base1 + n*8] = v1;
    }
}

extern "C" void kernel_launch(void* const* d_in, const int* in_sizes, int n_in,
                              void* d_out, int out_size) {
    const float* src  = (const float*)d_in[0];   // feat_1x_src [2,128,8,16,16]
    const float* dst  = (const float*)d_in[1];   // feat_2x_dst [2,128,16,32,32]
    const float* woff = (const float*)d_in[2];   // w_offset [648,256]
    const float* wdcn = (const float*)d_in[3];   // w_dcn [128,128,3,3,3]
    float* out = (float*)d_out;

    cudaFuncSetAttribute(k_dcn, cudaFuncAttributeMaxDynamicSharedMemorySize,
                         DCN_SMEM);

    const int NPREP = Bn*SDn*SHn*SWn*CSn + NTAP*128*CGn + MTILES*128*256 + NTAP;
    k_prep   <<<(NPREP + 255)/256, 256>>>(src, woff, wdcn);
    k_up     <<<Bn*(Pn/32), 256>>>(dst);
    k_offmma <<<Bn*MTILES*128, 256>>>();
    k_dcn    <<<Bn*(Pn/64), 256, DCN_SMEM>>>(out);
}